// round 1
// baseline (speedup 1.0000x reference)
#include <cuda_runtime.h>
#include <cstdint>

#define HIDDEN 256
#define HEADS 8
#define MAXN 50000
#define MAXE 800000

// ---------------- scratch (static device allocations, allowed) ----------------
__device__ float g_q[(size_t)MAXN * HIDDEN];
__device__ float g_k[(size_t)MAXN * HIDDEN];
__device__ float g_v[(size_t)MAXN * HIDDEN];
__device__ float g_ao[(size_t)MAXN * HIDDEN];
__device__ float g_s[(size_t)MAXE * HEADS];
__device__ int   g_deg[MAXN];
__device__ int   g_offs[MAXN + 1];
__device__ int   g_cursor[MAXN];
__device__ int   g_ccol[MAXE];

// ---------------- CSR build ----------------
__global__ void count_deg_kernel(const int* __restrict__ row, int e) {
    int i = blockIdx.x * blockDim.x + threadIdx.x;
    if (i < e) atomicAdd(&g_deg[row[i]], 1);
}

// single-block exclusive scan over g_deg -> g_offs, g_cursor
__global__ void scan_kernel(int n) {
    __shared__ int wsum[32];
    int lane = threadIdx.x & 31;
    int wid  = threadIdx.x >> 5;
    int carry = 0;
    for (int base = 0; base < n; base += 1024) {
        int i = base + (int)threadIdx.x;
        int v = (i < n) ? g_deg[i] : 0;
        int x = v;
        #pragma unroll
        for (int d = 1; d < 32; d <<= 1) {
            int y = __shfl_up_sync(0xffffffffu, x, d);
            if (lane >= d) x += y;
        }
        if (lane == 31) wsum[wid] = x;
        __syncthreads();
        if (wid == 0) {
            int wv = wsum[lane];
            #pragma unroll
            for (int d = 1; d < 32; d <<= 1) {
                int y = __shfl_up_sync(0xffffffffu, wv, d);
                if (lane >= d) wv += y;
            }
            wsum[lane] = wv;
        }
        __syncthreads();
        int inc = x + (wid > 0 ? wsum[wid - 1] : 0) + carry;
        if (i < n) {
            int excl = inc - v;
            g_offs[i]   = excl;
            g_cursor[i] = excl;
        }
        carry += wsum[31];
        __syncthreads();
    }
    if (threadIdx.x == 0) g_offs[n] = carry;
}

__global__ void scatter_kernel(const int* __restrict__ row, const int* __restrict__ col, int e) {
    int i = blockIdx.x * blockDim.x + threadIdx.x;
    if (i < e) {
        int slot = atomicAdd(&g_cursor[row[i]], 1);
        g_ccol[slot] = col[i];
    }
}

// ---------------- GEMM: C[m][o] = (sum_i A[m][i]*W[o][i] + bias[o]) * scale ----
// M x 256, K=256 fixed. BM=BN=64, BK=32, 256 threads, 4x4 microtile.
__global__ void __launch_bounds__(256) gemm_bias_kernel(
    const float* __restrict__ A, const float* __restrict__ W,
    const float* __restrict__ bias, float* __restrict__ C,
    int M, float scale)
{
    __shared__ float As[32][68];
    __shared__ float Bs[32][68];
    const int tid = threadIdx.x;
    const int m0 = blockIdx.x * 64;
    const int n0 = blockIdx.y * 64;
    const int ty = tid / 16;       // 0..15 -> row group
    const int tx = tid % 16;       // 0..15 -> col group
    const int lr = tid / 8;        // 0..31 load row
    const int lc = (tid % 8) * 4;  // 0..28 load col (float4)

    float acc[4][4] = {};

    for (int k0 = 0; k0 < HIDDEN; k0 += 32) {
        #pragma unroll
        for (int rr = 0; rr < 2; rr++) {
            int r = lr + rr * 32;
            int m = m0 + r;
            float4 av = make_float4(0.f, 0.f, 0.f, 0.f);
            if (m < M) av = *(const float4*)(A + (size_t)m * HIDDEN + k0 + lc);
            As[lc + 0][r] = av.x; As[lc + 1][r] = av.y;
            As[lc + 2][r] = av.z; As[lc + 3][r] = av.w;
            float4 bv = *(const float4*)(W + (size_t)(n0 + r) * HIDDEN + k0 + lc);
            Bs[lc + 0][r] = bv.x; Bs[lc + 1][r] = bv.y;
            Bs[lc + 2][r] = bv.z; Bs[lc + 3][r] = bv.w;
        }
        __syncthreads();
        #pragma unroll
        for (int kk = 0; kk < 32; kk++) {
            float4 a = *(const float4*)&As[kk][ty * 4];
            float4 b = *(const float4*)&Bs[kk][tx * 4];
            acc[0][0] += a.x * b.x; acc[0][1] += a.x * b.y; acc[0][2] += a.x * b.z; acc[0][3] += a.x * b.w;
            acc[1][0] += a.y * b.x; acc[1][1] += a.y * b.y; acc[1][2] += a.y * b.z; acc[1][3] += a.y * b.w;
            acc[2][0] += a.z * b.x; acc[2][1] += a.z * b.y; acc[2][2] += a.z * b.z; acc[2][3] += a.z * b.w;
            acc[3][0] += a.w * b.x; acc[3][1] += a.w * b.y; acc[3][2] += a.w * b.z; acc[3][3] += a.w * b.w;
        }
        __syncthreads();
    }

    float4 bb = *(const float4*)&bias[n0 + tx * 4];
    #pragma unroll
    for (int i = 0; i < 4; i++) {
        int m = m0 + ty * 4 + i;
        if (m < M) {
            float4 o;
            o.x = (acc[i][0] + bb.x) * scale;
            o.y = (acc[i][1] + bb.y) * scale;
            o.z = (acc[i][2] + bb.z) * scale;
            o.w = (acc[i][3] + bb.w) * scale;
            *(float4*)(C + (size_t)m * HIDDEN + n0 + tx * 4) = o;
        }
    }
}

// ---------------- attention: one warp per node ----------------
// feature f = c*32 + lane  -> head = lane % 8 (since 32 % 8 == 0)
__global__ void __launch_bounds__(256) attn_kernel(int n) {
    int gw   = (blockIdx.x * blockDim.x + threadIdx.x) >> 5;
    int lane = threadIdx.x & 31;
    if (gw >= n) return;
    const int i = gw;
    const int start = g_offs[i];
    const int end   = g_offs[i + 1];
    const int hh = lane & 7;

    float ql[8];
    #pragma unroll
    for (int c = 0; c < 8; c++) ql[c] = g_q[(size_t)i * HIDDEN + c * 32 + lane];

    // pass 1: SDDMM scores + running max per head
    float m = __int_as_float(0xff800000);  // -inf
    for (int p = start; p < end; p++) {
        int cn = g_ccol[p];
        const float* kr = &g_k[(size_t)cn * HIDDEN];
        float ps = 0.f;
        #pragma unroll
        for (int c = 0; c < 8; c++) ps += ql[c] * __ldg(&kr[c * 32 + lane]);
        ps += __shfl_xor_sync(0xffffffffu, ps, 16);
        ps += __shfl_xor_sync(0xffffffffu, ps, 8);
        // every lane now holds s[head = lane%8]
        m = fmaxf(m, ps);
        if (lane < 8) g_s[(size_t)p * 8 + lane] = ps;
    }

    // pass 2: exp, denom, weighted V accumulation
    float denom = 0.f;
    float acc[8] = {};
    for (int p = start; p < end; p++) {
        float sv = g_s[(size_t)p * 8 + hh];
        float w = __expf(sv - m);
        denom += w;
        int cn = g_ccol[p];
        const float* vr = &g_v[(size_t)cn * HIDDEN];
        #pragma unroll
        for (int c = 0; c < 8; c++) acc[c] += w * __ldg(&vr[c * 32 + lane]);
    }

    float rd = (end > start) ? 1.f / denom : 0.f;
    #pragma unroll
    for (int c = 0; c < 8; c++)
        g_ao[(size_t)i * HIDDEN + c * 32 + lane] = acc[c] * rd;
}

// ---------------- launch ----------------
extern "C" void kernel_launch(void* const* d_in, const int* in_sizes, int n_in,
                              void* d_out, int out_size) {
    const float* h   = (const float*)d_in[0];
    const int*   row = (const int*)d_in[1];
    const int*   col = (const int*)d_in[2];
    const float* Wq  = (const float*)d_in[3];
    const float* bq  = (const float*)d_in[4];
    const float* Wk  = (const float*)d_in[5];
    const float* bk  = (const float*)d_in[6];
    const float* Wv  = (const float*)d_in[7];
    const float* bv  = (const float*)d_in[8];
    const float* Wo  = (const float*)d_in[9];
    const float* bo  = (const float*)d_in[10];
    float* out = (float*)d_out;

    const int N = in_sizes[0] / HIDDEN;
    const int E = in_sizes[1];

    float *pq, *pk, *pv, *pao;
    int *pdeg;
    cudaGetSymbolAddress((void**)&pq,  g_q);
    cudaGetSymbolAddress((void**)&pk,  g_k);
    cudaGetSymbolAddress((void**)&pv,  g_v);
    cudaGetSymbolAddress((void**)&pao, g_ao);
    cudaGetSymbolAddress((void**)&pdeg, g_deg);

    cudaMemsetAsync(pdeg, 0, (size_t)N * sizeof(int));
    count_deg_kernel<<<(E + 255) / 256, 256>>>(row, E);
    scan_kernel<<<1, 1024>>>(N);
    scatter_kernel<<<(E + 255) / 256, 256>>>(row, col, E);

    dim3 gg((N + 63) / 64, HIDDEN / 64, 1);
    const float scaling = 0.17677669529663687f;  // 32^-0.5
    gemm_bias_kernel<<<gg, 256>>>(h, Wq, bq, pq, N, scaling);
    gemm_bias_kernel<<<gg, 256>>>(h, Wk, bk, pk, N, 1.f);
    gemm_bias_kernel<<<gg, 256>>>(h, Wv, bv, pv, N, 1.f);

    attn_kernel<<<(N + 7) / 8, 256>>>(N);

    gemm_bias_kernel<<<gg, 256>>>(pao, Wo, bo, out, N, 1.f);
}

// round 3
// speedup vs baseline: 1.2777x; 1.2777x over previous
#include <cuda_runtime.h>
#include <cstdint>

#define HIDDEN 256
#define HEADS 8
#define MAXN 50000
#define MAXE 800000

// ---------------- scratch (static device allocations, allowed) ----------------
__device__ float g_q[(size_t)MAXN * HIDDEN];
__device__ float g_k[(size_t)MAXN * HIDDEN];
__device__ float g_v[(size_t)MAXN * HIDDEN];
__device__ float g_ao[(size_t)MAXN * HIDDEN];
__device__ int   g_deg[MAXN];
__device__ int   g_offs[MAXN + 1];
__device__ int   g_cursor[MAXN];
__device__ int   g_ccol[MAXE];

// ---------------- CSR build ----------------
__global__ void count_deg_kernel(const int* __restrict__ row, int e) {
    int i = blockIdx.x * blockDim.x + threadIdx.x;
    if (i < e) atomicAdd(&g_deg[row[i]], 1);
}

__global__ void scan_kernel(int n) {
    __shared__ int wsum[32];
    int lane = threadIdx.x & 31;
    int wid  = threadIdx.x >> 5;
    int carry = 0;
    for (int base = 0; base < n; base += 1024) {
        int i = base + (int)threadIdx.x;
        int v = (i < n) ? g_deg[i] : 0;
        int x = v;
        #pragma unroll
        for (int d = 1; d < 32; d <<= 1) {
            int y = __shfl_up_sync(0xffffffffu, x, d);
            if (lane >= d) x += y;
        }
        if (lane == 31) wsum[wid] = x;
        __syncthreads();
        if (wid == 0) {
            int wv = wsum[lane];
            #pragma unroll
            for (int d = 1; d < 32; d <<= 1) {
                int y = __shfl_up_sync(0xffffffffu, wv, d);
                if (lane >= d) wv += y;
            }
            wsum[lane] = wv;
        }
        __syncthreads();
        int inc = x + (wid > 0 ? wsum[wid - 1] : 0) + carry;
        if (i < n) {
            int excl = inc - v;
            g_offs[i]   = excl;
            g_cursor[i] = excl;
        }
        carry += wsum[31];
        __syncthreads();
    }
    if (threadIdx.x == 0) g_offs[n] = carry;
}

__global__ void scatter_kernel(const int* __restrict__ row, const int* __restrict__ col, int e) {
    int i = blockIdx.x * blockDim.x + threadIdx.x;
    if (i < e) {
        int slot = atomicAdd(&g_cursor[row[i]], 1);
        g_ccol[slot] = col[i];
    }
}

// ---------------- 3xTF32 tensor-core GEMM ----------------
// C[m][n] = (sum_k A[m][k] * W[n][k] + bias[n]) * scale
// Operand split: x = hi + lo, hi = tf32(x), lo = tf32(x - hi).
// C ~= Ah*Bh + Al*Bh + Ah*Bl   (error ~2^-22, fp32-equivalent)
#define GPITCH 20

__device__ __forceinline__ uint32_t f2tf32(float x) {
    uint32_t r;
    asm("cvt.rna.tf32.f32 %0, %1;" : "=r"(r) : "f"(x));
    return r;
}

__global__ void __launch_bounds__(256) gemm_tf32x3_kernel(
    const float* __restrict__ A, const float* __restrict__ W,
    const float* __restrict__ bias, float* __restrict__ C,
    int M, float scale)
{
    __shared__ float As[128 * GPITCH];
    __shared__ float Bs[128 * GPITCH];

    const int tid  = threadIdx.x;
    const int lane = tid & 31;
    const int warp = tid >> 5;
    const int wm   = (warp >> 1) * 32;   // warp M offset (0,32,64,96)
    const int wn   = (warp & 1) * 64;    // warp N offset (0,64)
    const int g    = lane >> 2;          // 0..7
    const int tig  = lane & 3;           // 0..3

    const int m0 = blockIdx.x * 128;
    const int n0 = blockIdx.y * 128;

    const int lr = tid >> 2;             // 0..63 load row
    const int lk = (tid & 3) * 4;        // 0,4,8,12

    float acc[2][8][4];
    #pragma unroll
    for (int mt = 0; mt < 2; mt++)
        #pragma unroll
        for (int nt = 0; nt < 8; nt++)
            #pragma unroll
            for (int r = 0; r < 4; r++) acc[mt][nt][r] = 0.f;

    for (int k0 = 0; k0 < HIDDEN; k0 += 16) {
        #pragma unroll
        for (int half = 0; half < 2; half++) {
            int r = lr + half * 64;
            int m = m0 + r;
            float4 av = make_float4(0.f, 0.f, 0.f, 0.f);
            if (m < M) av = *(const float4*)(A + (size_t)m * HIDDEN + k0 + lk);
            As[r * GPITCH + lk + 0] = av.x;
            As[r * GPITCH + lk + 1] = av.y;
            As[r * GPITCH + lk + 2] = av.z;
            As[r * GPITCH + lk + 3] = av.w;
            float4 bv = *(const float4*)(W + (size_t)(n0 + r) * HIDDEN + k0 + lk);
            Bs[r * GPITCH + lk + 0] = bv.x;
            Bs[r * GPITCH + lk + 1] = bv.y;
            Bs[r * GPITCH + lk + 2] = bv.z;
            Bs[r * GPITCH + lk + 3] = bv.w;
        }
        __syncthreads();

        #pragma unroll
        for (int ks = 0; ks < 2; ks++) {
            const int kb = ks * 8;
            // A fragments (hi/lo): 2 m16 tiles
            uint32_t ah[2][4], al[2][4];
            #pragma unroll
            for (int mt = 0; mt < 2; mt++) {
                int rbase = wm + mt * 16;
                float x0 = As[(rbase + g) * GPITCH + kb + tig];
                float x1 = As[(rbase + g + 8) * GPITCH + kb + tig];
                float x2 = As[(rbase + g) * GPITCH + kb + tig + 4];
                float x3 = As[(rbase + g + 8) * GPITCH + kb + tig + 4];
                ah[mt][0] = f2tf32(x0); al[mt][0] = f2tf32(x0 - __uint_as_float(ah[mt][0]));
                ah[mt][1] = f2tf32(x1); al[mt][1] = f2tf32(x1 - __uint_as_float(ah[mt][1]));
                ah[mt][2] = f2tf32(x2); al[mt][2] = f2tf32(x2 - __uint_as_float(ah[mt][2]));
                ah[mt][3] = f2tf32(x3); al[mt][3] = f2tf32(x3 - __uint_as_float(ah[mt][3]));
            }
            // B fragments (hi/lo): 8 n8 tiles
            uint32_t bh[8][2], bl[8][2];
            #pragma unroll
            for (int nt = 0; nt < 8; nt++) {
                int nb = wn + nt * 8;
                float y0 = Bs[(nb + g) * GPITCH + kb + tig];
                float y1 = Bs[(nb + g) * GPITCH + kb + tig + 4];
                bh[nt][0] = f2tf32(y0); bl[nt][0] = f2tf32(y0 - __uint_as_float(bh[nt][0]));
                bh[nt][1] = f2tf32(y1); bl[nt][1] = f2tf32(y1 - __uint_as_float(bh[nt][1]));
            }
            #pragma unroll
            for (int mt = 0; mt < 2; mt++)
                #pragma unroll
                for (int nt = 0; nt < 8; nt++) {
                    // lo terms first, hi*hi last (better summation order)
                    asm volatile(
                        "mma.sync.aligned.m16n8k8.row.col.f32.tf32.tf32.f32 "
                        "{%0,%1,%2,%3}, {%4,%5,%6,%7}, {%8,%9}, {%0,%1,%2,%3};"
                        : "+f"(acc[mt][nt][0]), "+f"(acc[mt][nt][1]),
                          "+f"(acc[mt][nt][2]), "+f"(acc[mt][nt][3])
                        : "r"(al[mt][0]), "r"(al[mt][1]), "r"(al[mt][2]), "r"(al[mt][3]),
                          "r"(bh[nt][0]), "r"(bh[nt][1]));
                    asm volatile(
                        "mma.sync.aligned.m16n8k8.row.col.f32.tf32.tf32.f32 "
                        "{%0,%1,%2,%3}, {%4,%5,%6,%7}, {%8,%9}, {%0,%1,%2,%3};"
                        : "+f"(acc[mt][nt][0]), "+f"(acc[mt][nt][1]),
                          "+f"(acc[mt][nt][2]), "+f"(acc[mt][nt][3])
                        : "r"(ah[mt][0]), "r"(ah[mt][1]), "r"(ah[mt][2]), "r"(ah[mt][3]),
                          "r"(bl[nt][0]), "r"(bl[nt][1]));
                    asm volatile(
                        "mma.sync.aligned.m16n8k8.row.col.f32.tf32.tf32.f32 "
                        "{%0,%1,%2,%3}, {%4,%5,%6,%7}, {%8,%9}, {%0,%1,%2,%3};"
                        : "+f"(acc[mt][nt][0]), "+f"(acc[mt][nt][1]),
                          "+f"(acc[mt][nt][2]), "+f"(acc[mt][nt][3])
                        : "r"(ah[mt][0]), "r"(ah[mt][1]), "r"(ah[mt][2]), "r"(ah[mt][3]),
                          "r"(bh[nt][0]), "r"(bh[nt][1]));
                }
        }
        __syncthreads();
    }

    // epilogue
    #pragma unroll
    for (int mt = 0; mt < 2; mt++) {
        int r0 = m0 + wm + mt * 16 + g;
        #pragma unroll
        for (int nt = 0; nt < 8; nt++) {
            int c = n0 + wn + nt * 8 + 2 * tig;
            float bx = bias[c], by = bias[c + 1];
            if (r0 < M) {
                float2 o0;
                o0.x = (acc[mt][nt][0] + bx) * scale;
                o0.y = (acc[mt][nt][1] + by) * scale;
                *(float2*)(C + (size_t)r0 * HIDDEN + c) = o0;
            }
            if (r0 + 8 < M) {
                float2 o1;
                o1.x = (acc[mt][nt][2] + bx) * scale;
                o1.y = (acc[mt][nt][3] + by) * scale;
                *(float2*)(C + (size_t)(r0 + 8) * HIDDEN + c) = o1;
            }
        }
    }
}

// ---------------- attention: one warp per node, online softmax ----------------
// feature f = c*32 + lane  -> head = lane % 8 (since 32 % 8 == 0)
__global__ void __launch_bounds__(256) attn_kernel(int n) {
    int gw   = (blockIdx.x * blockDim.x + threadIdx.x) >> 5;
    int lane = threadIdx.x & 31;
    if (gw >= n) return;
    const int i = gw;
    const int start = g_offs[i];
    const int end   = g_offs[i + 1];

    float ql[8];
    #pragma unroll
    for (int c = 0; c < 8; c++) ql[c] = g_q[(size_t)i * HIDDEN + c * 32 + lane];

    float m = __int_as_float(0xff800000);  // -inf for this lane's head
    float d = 0.f;
    float acc[8] = {};

    for (int p = start; p < end; p++) {
        int cn = g_ccol[p];
        const float* kr = &g_k[(size_t)cn * HIDDEN];
        float ps = 0.f;
        #pragma unroll
        for (int c = 0; c < 8; c++) ps += ql[c] * __ldg(&kr[c * 32 + lane]);
        ps += __shfl_xor_sync(0xffffffffu, ps, 16);
        ps += __shfl_xor_sync(0xffffffffu, ps, 8);
        // every lane now holds s[head = lane%8]

        float nm = fmaxf(m, ps);
        float cf = __expf(m - nm);    // correction, 1.0 when max unchanged
        float w  = __expf(ps - nm);
        d = d * cf + w;
        m = nm;

        const float* vr = &g_v[(size_t)cn * HIDDEN];
        #pragma unroll
        for (int c = 0; c < 8; c++)
            acc[c] = acc[c] * cf + w * __ldg(&vr[c * 32 + lane]);
    }

    float rd = (end > start) ? 1.f / d : 0.f;
    #pragma unroll
    for (int c = 0; c < 8; c++)
        g_ao[(size_t)i * HIDDEN + c * 32 + lane] = acc[c] * rd;
}

// ---------------- launch ----------------
extern "C" void kernel_launch(void* const* d_in, const int* in_sizes, int n_in,
                              void* d_out, int out_size) {
    const float* h   = (const float*)d_in[0];
    const int*   row = (const int*)d_in[1];
    const int*   col = (const int*)d_in[2];
    const float* Wq  = (const float*)d_in[3];
    const float* bq  = (const float*)d_in[4];
    const float* Wk  = (const float*)d_in[5];
    const float* bk  = (const float*)d_in[6];
    const float* Wv  = (const float*)d_in[7];
    const float* bv  = (const float*)d_in[8];
    const float* Wo  = (const float*)d_in[9];
    const float* bo  = (const float*)d_in[10];
    float* out = (float*)d_out;

    const int N = in_sizes[0] / HIDDEN;
    const int E = in_sizes[1];

    float *pq, *pk, *pv, *pao;
    int *pdeg;
    cudaGetSymbolAddress((void**)&pq,  g_q);
    cudaGetSymbolAddress((void**)&pk,  g_k);
    cudaGetSymbolAddress((void**)&pv,  g_v);
    cudaGetSymbolAddress((void**)&pao, g_ao);
    cudaGetSymbolAddress((void**)&pdeg, g_deg);

    cudaMemsetAsync(pdeg, 0, (size_t)N * sizeof(int));
    count_deg_kernel<<<(E + 255) / 256, 256>>>(row, E);
    scan_kernel<<<1, 1024>>>(N);
    scatter_kernel<<<(E + 255) / 256, 256>>>(row, col, E);

    dim3 gg((N + 127) / 128, HIDDEN / 128, 1);
    const float scaling = 0.17677669529663687f;  // 32^-0.5
    gemm_tf32x3_kernel<<<gg, 256>>>(h, Wq, bq, pq, N, scaling);
    gemm_tf32x3_kernel<<<gg, 256>>>(h, Wk, bk, pk, N, 1.f);
    gemm_tf32x3_kernel<<<gg, 256>>>(h, Wv, bv, pv, N, 1.f);

    attn_kernel<<<(N + 7) / 8, 256>>>(N);

    gemm_tf32x3_kernel<<<gg, 256>>>(pao, Wo, bo, out, N, 1.f);
}

// round 4
// speedup vs baseline: 1.3081x; 1.0237x over previous
#include <cuda_runtime.h>
#include <cstdint>

#define HIDDEN 256
#define HEADS 8
#define MAXN 50000
#define MAXE 800000

// ---------------- scratch ----------------
__device__ float g_q[(size_t)MAXN * HIDDEN];
__device__ float g_k[(size_t)MAXN * HIDDEN];
__device__ float g_v[(size_t)MAXN * HIDDEN];
__device__ float g_ao[(size_t)MAXN * HIDDEN];
__device__ int   g_deg[MAXN];
__device__ int   g_offs[MAXN + 1];
__device__ int   g_cursor[MAXN];
__device__ int   g_ccol[MAXE];

// ---------------- CSR build ----------------
__global__ void count_deg_kernel(const int* __restrict__ row, int e) {
    int i = blockIdx.x * blockDim.x + threadIdx.x;
    if (i < e) atomicAdd(&g_deg[row[i]], 1);
}

__global__ void scan_kernel(int n) {
    __shared__ int wsum[32];
    int lane = threadIdx.x & 31;
    int wid  = threadIdx.x >> 5;
    int carry = 0;
    for (int base = 0; base < n; base += 1024) {
        int i = base + (int)threadIdx.x;
        int v = (i < n) ? g_deg[i] : 0;
        int x = v;
        #pragma unroll
        for (int d = 1; d < 32; d <<= 1) {
            int y = __shfl_up_sync(0xffffffffu, x, d);
            if (lane >= d) x += y;
        }
        if (lane == 31) wsum[wid] = x;
        __syncthreads();
        if (wid == 0) {
            int wv = wsum[lane];
            #pragma unroll
            for (int d = 1; d < 32; d <<= 1) {
                int y = __shfl_up_sync(0xffffffffu, wv, d);
                if (lane >= d) wv += y;
            }
            wsum[lane] = wv;
        }
        __syncthreads();
        int inc = x + (wid > 0 ? wsum[wid - 1] : 0) + carry;
        if (i < n) {
            int excl = inc - v;
            g_offs[i]   = excl;
            g_cursor[i] = excl;
        }
        carry += wsum[31];
        __syncthreads();
    }
    if (threadIdx.x == 0) g_offs[n] = carry;
}

__global__ void scatter_kernel(const int* __restrict__ row, const int* __restrict__ col, int e) {
    int i = blockIdx.x * blockDim.x + threadIdx.x;
    if (i < e) {
        int slot = atomicAdd(&g_cursor[row[i]], 1);
        g_ccol[slot] = col[i];
    }
}

// ---------------- 3xTF32 GEMM, double-buffered, pre-split smem ----------------
// BM=128 BN=64 BK=16, 8 warps, warp tile 32x32.
// blockIdx.z selects (W, bias, C): fused QKV in one launch.
#define PITCH 20
#define A_SZ (128 * PITCH)          // 2560 floats
#define B_SZ (64 * PITCH)           // 1280 floats
#define STAGE_SZ (2 * A_SZ + 2 * B_SZ)   // 7680 floats = 30720 B
#define SMEM_BYTES (2 * STAGE_SZ * 4)    // 61440 B

__device__ __forceinline__ float tf32f(float x) {
    uint32_t r;
    asm("cvt.rna.tf32.f32 %0, %1;" : "=r"(r) : "f"(x));
    return __uint_as_float(r);
}

__device__ __forceinline__ void split_store4(float* hi, float* lo, int idx, float4 v) {
    float4 h, l;
    h.x = tf32f(v.x); l.x = tf32f(v.x - h.x);
    h.y = tf32f(v.y); l.y = tf32f(v.y - h.y);
    h.z = tf32f(v.z); l.z = tf32f(v.z - h.z);
    h.w = tf32f(v.w); l.w = tf32f(v.w - h.w);
    *(float4*)(hi + idx) = h;
    *(float4*)(lo + idx) = l;
}

#define MMA_TF32(ACC, AV, BV)                                              \
    asm volatile(                                                          \
        "mma.sync.aligned.m16n8k8.row.col.f32.tf32.tf32.f32 "             \
        "{%0,%1,%2,%3}, {%4,%5,%6,%7}, {%8,%9}, {%0,%1,%2,%3};"           \
        : "+f"(ACC[0]), "+f"(ACC[1]), "+f"(ACC[2]), "+f"(ACC[3])          \
        : "r"(AV[0]), "r"(AV[1]), "r"(AV[2]), "r"(AV[3]),                 \
          "r"(BV[0]), "r"(BV[1]))

__global__ void __launch_bounds__(256) gemm3_kernel(
    const float* __restrict__ A,
    const float* __restrict__ W0, const float* __restrict__ W1, const float* __restrict__ W2,
    const float* __restrict__ b0, const float* __restrict__ b1, const float* __restrict__ b2,
    float* __restrict__ C0, float* __restrict__ C1, float* __restrict__ C2,
    int M, float scale0)
{
    extern __shared__ float smem[];

    const int z = blockIdx.z;
    const float* W    = (z == 0) ? W0 : (z == 1) ? W1 : W2;
    const float* bias = (z == 0) ? b0 : (z == 1) ? b1 : b2;
    float* C          = (z == 0) ? C0 : (z == 1) ? C1 : C2;
    const float scale = (z == 0) ? scale0 : 1.f;

    const int tid  = threadIdx.x;
    const int lane = tid & 31;
    const int warp = tid >> 5;
    const int wm   = (warp >> 1) * 32;
    const int wn   = (warp & 1) * 32;
    const int g    = lane >> 2;
    const int tig  = lane & 3;

    const int m0 = blockIdx.x * 128;
    const int n0 = blockIdx.y * 64;

    const int lr = tid >> 2;            // 0..63
    const int lk = (tid & 3) * 4;       // 0,4,8,12

    float acc[2][4][4];
    #pragma unroll
    for (int mt = 0; mt < 2; mt++)
        #pragma unroll
        for (int nt = 0; nt < 4; nt++)
            #pragma unroll
            for (int r = 0; r < 4; r++) acc[mt][nt][r] = 0.f;

    const int mA0 = m0 + lr, mA1 = m0 + lr + 64;
    const float* Arow0 = A + (size_t)mA0 * HIDDEN + lk;
    const float* Arow1 = A + (size_t)mA1 * HIDDEN + lk;
    const float* Wrow  = W + (size_t)(n0 + lr) * HIDDEN + lk;

    float4 ra0, ra1, rb;

    // prologue: load k0 = 0
    ra0 = (mA0 < M) ? *(const float4*)(Arow0) : make_float4(0,0,0,0);
    ra1 = (mA1 < M) ? *(const float4*)(Arow1) : make_float4(0,0,0,0);
    rb  = *(const float4*)(Wrow);
    {
        float* Ah = smem;             float* Al = smem + A_SZ;
        float* Bh = smem + 2 * A_SZ;  float* Bl = smem + 2 * A_SZ + B_SZ;
        split_store4(Ah, Al, lr * PITCH + lk, ra0);
        split_store4(Ah, Al, (lr + 64) * PITCH + lk, ra1);
        split_store4(Bh, Bl, lr * PITCH + lk, rb);
    }
    __syncthreads();

    #pragma unroll 4
    for (int it = 0; it < 16; it++) {
        // issue loads for next tile
        if (it + 1 < 16) {
            int ko = (it + 1) * 16;
            ra0 = (mA0 < M) ? *(const float4*)(Arow0 + ko) : make_float4(0,0,0,0);
            ra1 = (mA1 < M) ? *(const float4*)(Arow1 + ko) : make_float4(0,0,0,0);
            rb  = *(const float4*)(Wrow + ko);
        }

        // compute current stage
        {
            const float* base = smem + (it & 1) * STAGE_SZ;
            const float* Ah = base;             const float* Al = base + A_SZ;
            const float* Bh = base + 2 * A_SZ;  const float* Bl = base + 2 * A_SZ + B_SZ;

            #pragma unroll
            for (int ks = 0; ks < 2; ks++) {
                const int kb = ks * 8;
                uint32_t ah[2][4], al[2][4];
                #pragma unroll
                for (int mt = 0; mt < 2; mt++) {
                    int rbase = wm + mt * 16;
                    ah[mt][0] = __float_as_uint(Ah[(rbase + g) * PITCH + kb + tig]);
                    ah[mt][1] = __float_as_uint(Ah[(rbase + g + 8) * PITCH + kb + tig]);
                    ah[mt][2] = __float_as_uint(Ah[(rbase + g) * PITCH + kb + tig + 4]);
                    ah[mt][3] = __float_as_uint(Ah[(rbase + g + 8) * PITCH + kb + tig + 4]);
                    al[mt][0] = __float_as_uint(Al[(rbase + g) * PITCH + kb + tig]);
                    al[mt][1] = __float_as_uint(Al[(rbase + g + 8) * PITCH + kb + tig]);
                    al[mt][2] = __float_as_uint(Al[(rbase + g) * PITCH + kb + tig + 4]);
                    al[mt][3] = __float_as_uint(Al[(rbase + g + 8) * PITCH + kb + tig + 4]);
                }
                #pragma unroll
                for (int nt = 0; nt < 4; nt++) {
                    int nb = wn + nt * 8;
                    uint32_t bh[2], bl[2];
                    bh[0] = __float_as_uint(Bh[(nb + g) * PITCH + kb + tig]);
                    bh[1] = __float_as_uint(Bh[(nb + g) * PITCH + kb + tig + 4]);
                    bl[0] = __float_as_uint(Bl[(nb + g) * PITCH + kb + tig]);
                    bl[1] = __float_as_uint(Bl[(nb + g) * PITCH + kb + tig + 4]);
                    #pragma unroll
                    for (int mt = 0; mt < 2; mt++) {
                        MMA_TF32(acc[mt][nt], al[mt], bh);
                        MMA_TF32(acc[mt][nt], ah[mt], bl);
                        MMA_TF32(acc[mt][nt], ah[mt], bh);
                    }
                }
            }
        }

        // store next stage
        if (it + 1 < 16) {
            float* base = smem + ((it + 1) & 1) * STAGE_SZ;
            float* Ah = base;             float* Al = base + A_SZ;
            float* Bh = base + 2 * A_SZ;  float* Bl = base + 2 * A_SZ + B_SZ;
            split_store4(Ah, Al, lr * PITCH + lk, ra0);
            split_store4(Ah, Al, (lr + 64) * PITCH + lk, ra1);
            split_store4(Bh, Bl, lr * PITCH + lk, rb);
        }
        __syncthreads();
    }

    // epilogue
    #pragma unroll
    for (int mt = 0; mt < 2; mt++) {
        int r0 = m0 + wm + mt * 16 + g;
        #pragma unroll
        for (int nt = 0; nt < 4; nt++) {
            int c = n0 + wn + nt * 8 + 2 * tig;
            float bx = bias[c], by = bias[c + 1];
            if (r0 < M) {
                float2 o0;
                o0.x = (acc[mt][nt][0] + bx) * scale;
                o0.y = (acc[mt][nt][1] + by) * scale;
                *(float2*)(C + (size_t)r0 * HIDDEN + c) = o0;
            }
            if (r0 + 8 < M) {
                float2 o1;
                o1.x = (acc[mt][nt][2] + bx) * scale;
                o1.y = (acc[mt][nt][3] + by) * scale;
                *(float2*)(C + (size_t)(r0 + 8) * HIDDEN + c) = o1;
            }
        }
    }
}

// ---------------- attention: one warp per node, paired-edge online softmax ----
__global__ void __launch_bounds__(256) attn_kernel(int n) {
    int gw   = (blockIdx.x * blockDim.x + threadIdx.x) >> 5;
    int lane = threadIdx.x & 31;
    if (gw >= n) return;
    const int i = gw;
    const int start = g_offs[i];
    const int end   = g_offs[i + 1];

    float ql[8];
    #pragma unroll
    for (int c = 0; c < 8; c++) ql[c] = g_q[(size_t)i * HIDDEN + c * 32 + lane];

    float m = __int_as_float(0xff800000);
    float d = 0.f;
    float acc[8] = {};

    int p = start;
    for (; p + 1 < end; p += 2) {
        int c0 = g_ccol[p], c1 = g_ccol[p + 1];
        const float* k0r = &g_k[(size_t)c0 * HIDDEN];
        const float* k1r = &g_k[(size_t)c1 * HIDDEN];
        float s0 = 0.f, s1 = 0.f;
        #pragma unroll
        for (int c = 0; c < 8; c++) {
            float kv0 = __ldg(&k0r[c * 32 + lane]);
            float kv1 = __ldg(&k1r[c * 32 + lane]);
            s0 += ql[c] * kv0;
            s1 += ql[c] * kv1;
        }
        s0 += __shfl_xor_sync(0xffffffffu, s0, 16);
        s0 += __shfl_xor_sync(0xffffffffu, s0, 8);
        s1 += __shfl_xor_sync(0xffffffffu, s1, 16);
        s1 += __shfl_xor_sync(0xffffffffu, s1, 8);

        float m2 = fmaxf(m, fmaxf(s0, s1));
        float cf = __expf(m - m2);
        float w0 = __expf(s0 - m2);
        float w1 = __expf(s1 - m2);
        d = d * cf + w0 + w1;
        m = m2;

        const float* v0r = &g_v[(size_t)c0 * HIDDEN];
        const float* v1r = &g_v[(size_t)c1 * HIDDEN];
        #pragma unroll
        for (int c = 0; c < 8; c++) {
            float vv0 = __ldg(&v0r[c * 32 + lane]);
            float vv1 = __ldg(&v1r[c * 32 + lane]);
            acc[c] = acc[c] * cf + w0 * vv0 + w1 * vv1;
        }
    }
    if (p < end) {
        int c0 = g_ccol[p];
        const float* kr = &g_k[(size_t)c0 * HIDDEN];
        float s0 = 0.f;
        #pragma unroll
        for (int c = 0; c < 8; c++) s0 += ql[c] * __ldg(&kr[c * 32 + lane]);
        s0 += __shfl_xor_sync(0xffffffffu, s0, 16);
        s0 += __shfl_xor_sync(0xffffffffu, s0, 8);
        float m2 = fmaxf(m, s0);
        float cf = __expf(m - m2);
        float w0 = __expf(s0 - m2);
        d = d * cf + w0;
        m = m2;
        const float* vr = &g_v[(size_t)c0 * HIDDEN];
        #pragma unroll
        for (int c = 0; c < 8; c++)
            acc[c] = acc[c] * cf + w0 * __ldg(&vr[c * 32 + lane]);
    }

    float rd = (end > start) ? 1.f / d : 0.f;
    #pragma unroll
    for (int c = 0; c < 8; c++)
        g_ao[(size_t)i * HIDDEN + c * 32 + lane] = acc[c] * rd;
}

// ---------------- launch ----------------
extern "C" void kernel_launch(void* const* d_in, const int* in_sizes, int n_in,
                              void* d_out, int out_size) {
    const float* h   = (const float*)d_in[0];
    const int*   row = (const int*)d_in[1];
    const int*   col = (const int*)d_in[2];
    const float* Wq  = (const float*)d_in[3];
    const float* bq  = (const float*)d_in[4];
    const float* Wk  = (const float*)d_in[5];
    const float* bk  = (const float*)d_in[6];
    const float* Wv  = (const float*)d_in[7];
    const float* bv  = (const float*)d_in[8];
    const float* Wo  = (const float*)d_in[9];
    const float* bo  = (const float*)d_in[10];
    float* out = (float*)d_out;

    const int N = in_sizes[0] / HIDDEN;
    const int E = in_sizes[1];

    float *pq, *pk, *pv, *pao;
    int *pdeg;
    cudaGetSymbolAddress((void**)&pq,  g_q);
    cudaGetSymbolAddress((void**)&pk,  g_k);
    cudaGetSymbolAddress((void**)&pv,  g_v);
    cudaGetSymbolAddress((void**)&pao, g_ao);
    cudaGetSymbolAddress((void**)&pdeg, g_deg);

    static int attr_set = 0;
    if (!attr_set) {
        cudaFuncSetAttribute(gemm3_kernel,
                             cudaFuncAttributeMaxDynamicSharedMemorySize, SMEM_BYTES);
        attr_set = 1;
    }

    cudaMemsetAsync(pdeg, 0, (size_t)N * sizeof(int));
    count_deg_kernel<<<(E + 255) / 256, 256>>>(row, E);
    scan_kernel<<<1, 1024>>>(N);
    scatter_kernel<<<(E + 255) / 256, 256>>>(row, col, E);

    const float scaling = 0.17677669529663687f;  // 32^-0.5
    dim3 gqkv((N + 127) / 128, HIDDEN / 64, 3);
    gemm3_kernel<<<gqkv, 256, SMEM_BYTES>>>(h, Wq, Wk, Wv, bq, bk, bv,
                                            pq, pk, pv, N, scaling);

    attn_kernel<<<(N + 7) / 8, 256>>>(N);

    dim3 go((N + 127) / 128, HIDDEN / 64, 1);
    gemm3_kernel<<<go, 256, SMEM_BYTES>>>(pao, Wo, Wo, Wo, bo, bo, bo,
                                          out, out, out, N, 1.f);
}

// round 6
// speedup vs baseline: 1.3954x; 1.0667x over previous
#include <cuda_runtime.h>
#include <cstdint>

#define HIDDEN 256
#define HEADS 8
#define MAXN 50000
#define MAXE 800000

// ---------------- scratch ----------------
__device__ float g_q[(size_t)MAXN * HIDDEN];
__device__ float g_k[(size_t)MAXN * HIDDEN];
__device__ float g_v[(size_t)MAXN * HIDDEN];
__device__ float g_ao[(size_t)MAXN * HIDDEN];
__device__ int   g_deg[MAXN];
__device__ int   g_offs[MAXN + 1];
__device__ int   g_cursor[MAXN];
__device__ int   g_ccol[MAXE];

// ---------------- CSR build ----------------
__global__ void count_deg_kernel(const int* __restrict__ row, int e) {
    int i = blockIdx.x * blockDim.x + threadIdx.x;
    if (i < e) atomicAdd(&g_deg[row[i]], 1);
}

__global__ void scan_kernel(int n) {
    __shared__ int wsum[32];
    int lane = threadIdx.x & 31;
    int wid  = threadIdx.x >> 5;
    int carry = 0;
    for (int base = 0; base < n; base += 1024) {
        int i = base + (int)threadIdx.x;
        int v = (i < n) ? g_deg[i] : 0;
        int x = v;
        #pragma unroll
        for (int d = 1; d < 32; d <<= 1) {
            int y = __shfl_up_sync(0xffffffffu, x, d);
            if (lane >= d) x += y;
        }
        if (lane == 31) wsum[wid] = x;
        __syncthreads();
        if (wid == 0) {
            int wv = wsum[lane];
            #pragma unroll
            for (int d = 1; d < 32; d <<= 1) {
                int y = __shfl_up_sync(0xffffffffu, wv, d);
                if (lane >= d) wv += y;
            }
            wsum[lane] = wv;
        }
        __syncthreads();
        int inc = x + (wid > 0 ? wsum[wid - 1] : 0) + carry;
        if (i < n) {
            int excl = inc - v;
            g_offs[i]   = excl;
            g_cursor[i] = excl;
        }
        carry += wsum[31];
        __syncthreads();
    }
    if (threadIdx.x == 0) g_offs[n] = carry;
}

__global__ void scatter_kernel(const int* __restrict__ row, const int* __restrict__ col, int e) {
    int i = blockIdx.x * blockDim.x + threadIdx.x;
    if (i < e) {
        int slot = atomicAdd(&g_cursor[row[i]], 1);
        g_ccol[slot] = col[i];
    }
}

// ---------------- 3xTF32 GEMM, double-buffered, pre-split smem ----------------
// BM=128 BN=64 BK=16, 8 warps, warp tile 32x32.
// blockIdx.z selects (W, bias, C): fused QKV in one launch.
#define PITCH 20
#define A_SZ (128 * PITCH)
#define B_SZ (64 * PITCH)
#define STAGE_SZ (2 * A_SZ + 2 * B_SZ)
#define SMEM_BYTES (2 * STAGE_SZ * 4)

__device__ __forceinline__ float tf32f(float x) {
    uint32_t r;
    asm("cvt.rna.tf32.f32 %0, %1;" : "=r"(r) : "f"(x));
    return __uint_as_float(r);
}

__device__ __forceinline__ void split_store4(float* hi, float* lo, int idx, float4 v) {
    float4 h, l;
    h.x = tf32f(v.x); l.x = tf32f(v.x - h.x);
    h.y = tf32f(v.y); l.y = tf32f(v.y - h.y);
    h.z = tf32f(v.z); l.z = tf32f(v.z - h.z);
    h.w = tf32f(v.w); l.w = tf32f(v.w - h.w);
    *(float4*)(hi + idx) = h;
    *(float4*)(lo + idx) = l;
}

#define MMA_TF32(ACC, AV, BV)                                              \
    asm volatile(                                                          \
        "mma.sync.aligned.m16n8k8.row.col.f32.tf32.tf32.f32 "             \
        "{%0,%1,%2,%3}, {%4,%5,%6,%7}, {%8,%9}, {%0,%1,%2,%3};"           \
        : "+f"(ACC[0]), "+f"(ACC[1]), "+f"(ACC[2]), "+f"(ACC[3])          \
        : "r"(AV[0]), "r"(AV[1]), "r"(AV[2]), "r"(AV[3]),                 \
          "r"(BV[0]), "r"(BV[1]))

__global__ void __launch_bounds__(256, 3) gemm3_kernel(
    const float* __restrict__ A,
    const float* __restrict__ W0, const float* __restrict__ W1, const float* __restrict__ W2,
    const float* __restrict__ b0, const float* __restrict__ b1, const float* __restrict__ b2,
    float* __restrict__ C0, float* __restrict__ C1, float* __restrict__ C2,
    int M, float scale0)
{
    extern __shared__ float smem[];

    const int z = blockIdx.z;
    const float* W    = (z == 0) ? W0 : (z == 1) ? W1 : W2;
    const float* bias = (z == 0) ? b0 : (z == 1) ? b1 : b2;
    float* C          = (z == 0) ? C0 : (z == 1) ? C1 : C2;
    const float scale = (z == 0) ? scale0 : 1.f;

    const int tid  = threadIdx.x;
    const int lane = tid & 31;
    const int warp = tid >> 5;
    const int wm   = (warp >> 1) * 32;
    const int wn   = (warp & 1) * 32;
    const int g    = lane >> 2;
    const int tig  = lane & 3;

    const int m0 = blockIdx.x * 128;
    const int n0 = blockIdx.y * 64;

    const int lr = tid >> 2;
    const int lk = (tid & 3) * 4;

    float acc[2][4][4];
    #pragma unroll
    for (int mt = 0; mt < 2; mt++)
        #pragma unroll
        for (int nt = 0; nt < 4; nt++)
            #pragma unroll
            for (int r = 0; r < 4; r++) acc[mt][nt][r] = 0.f;

    const int mA0 = m0 + lr, mA1 = m0 + lr + 64;
    const float* Arow0 = A + (size_t)mA0 * HIDDEN + lk;
    const float* Arow1 = A + (size_t)mA1 * HIDDEN + lk;
    const float* Wrow  = W + (size_t)(n0 + lr) * HIDDEN + lk;

    float4 ra0, ra1, rb;

    ra0 = (mA0 < M) ? *(const float4*)(Arow0) : make_float4(0,0,0,0);
    ra1 = (mA1 < M) ? *(const float4*)(Arow1) : make_float4(0,0,0,0);
    rb  = *(const float4*)(Wrow);
    {
        float* Ah = smem;             float* Al = smem + A_SZ;
        float* Bh = smem + 2 * A_SZ;  float* Bl = smem + 2 * A_SZ + B_SZ;
        split_store4(Ah, Al, lr * PITCH + lk, ra0);
        split_store4(Ah, Al, (lr + 64) * PITCH + lk, ra1);
        split_store4(Bh, Bl, lr * PITCH + lk, rb);
    }
    __syncthreads();

    #pragma unroll 4
    for (int it = 0; it < 16; it++) {
        if (it + 1 < 16) {
            int ko = (it + 1) * 16;
            ra0 = (mA0 < M) ? *(const float4*)(Arow0 + ko) : make_float4(0,0,0,0);
            ra1 = (mA1 < M) ? *(const float4*)(Arow1 + ko) : make_float4(0,0,0,0);
            rb  = *(const float4*)(Wrow + ko);
        }

        {
            const float* base = smem + (it & 1) * STAGE_SZ;
            const float* Ah = base;             const float* Al = base + A_SZ;
            const float* Bh = base + 2 * A_SZ;  const float* Bl = base + 2 * A_SZ + B_SZ;

            #pragma unroll
            for (int ks = 0; ks < 2; ks++) {
                const int kb = ks * 8;
                uint32_t ah[2][4], al[2][4];
                #pragma unroll
                for (int mt = 0; mt < 2; mt++) {
                    int rbase = wm + mt * 16;
                    ah[mt][0] = __float_as_uint(Ah[(rbase + g) * PITCH + kb + tig]);
                    ah[mt][1] = __float_as_uint(Ah[(rbase + g + 8) * PITCH + kb + tig]);
                    ah[mt][2] = __float_as_uint(Ah[(rbase + g) * PITCH + kb + tig + 4]);
                    ah[mt][3] = __float_as_uint(Ah[(rbase + g + 8) * PITCH + kb + tig + 4]);
                    al[mt][0] = __float_as_uint(Al[(rbase + g) * PITCH + kb + tig]);
                    al[mt][1] = __float_as_uint(Al[(rbase + g + 8) * PITCH + kb + tig]);
                    al[mt][2] = __float_as_uint(Al[(rbase + g) * PITCH + kb + tig + 4]);
                    al[mt][3] = __float_as_uint(Al[(rbase + g + 8) * PITCH + kb + tig + 4]);
                }
                #pragma unroll
                for (int nt = 0; nt < 4; nt++) {
                    int nb = wn + nt * 8;
                    uint32_t bh[2], bl[2];
                    bh[0] = __float_as_uint(Bh[(nb + g) * PITCH + kb + tig]);
                    bh[1] = __float_as_uint(Bh[(nb + g) * PITCH + kb + tig + 4]);
                    bl[0] = __float_as_uint(Bl[(nb + g) * PITCH + kb + tig]);
                    bl[1] = __float_as_uint(Bl[(nb + g) * PITCH + kb + tig + 4]);
                    #pragma unroll
                    for (int mt = 0; mt < 2; mt++) {
                        MMA_TF32(acc[mt][nt], al[mt], bh);
                        MMA_TF32(acc[mt][nt], ah[mt], bl);
                        MMA_TF32(acc[mt][nt], ah[mt], bh);
                    }
                }
            }
        }

        if (it + 1 < 16) {
            float* base = smem + ((it + 1) & 1) * STAGE_SZ;
            float* Ah = base;             float* Al = base + A_SZ;
            float* Bh = base + 2 * A_SZ;  float* Bl = base + 2 * A_SZ + B_SZ;
            split_store4(Ah, Al, lr * PITCH + lk, ra0);
            split_store4(Ah, Al, (lr + 64) * PITCH + lk, ra1);
            split_store4(Bh, Bl, lr * PITCH + lk, rb);
        }
        __syncthreads();
    }

    #pragma unroll
    for (int mt = 0; mt < 2; mt++) {
        int r0 = m0 + wm + mt * 16 + g;
        #pragma unroll
        for (int nt = 0; nt < 4; nt++) {
            int c = n0 + wn + nt * 8 + 2 * tig;
            float bx = bias[c], by = bias[c + 1];
            if (r0 < M) {
                float2 o0;
                o0.x = (acc[mt][nt][0] + bx) * scale;
                o0.y = (acc[mt][nt][1] + by) * scale;
                *(float2*)(C + (size_t)r0 * HIDDEN + c) = o0;
            }
            if (r0 + 8 < M) {
                float2 o1;
                o1.x = (acc[mt][nt][2] + bx) * scale;
                o1.y = (acc[mt][nt][3] + by) * scale;
                *(float2*)(C + (size_t)(r0 + 8) * HIDDEN + c) = o1;
            }
        }
    }
}

// ---------------- attention: one warp per node, 4-edge online softmax -------
// feature f = c*32 + lane -> head = lane % 8
__global__ void __launch_bounds__(256) attn_kernel(int n) {
    int gw   = (blockIdx.x * blockDim.x + threadIdx.x) >> 5;
    int lane = threadIdx.x & 31;
    if (gw >= n) return;
    const int i = gw;
    const int start = g_offs[i];
    const int end   = g_offs[i + 1];

    float ql[8];
    #pragma unroll
    for (int c = 0; c < 8; c++) ql[c] = g_q[(size_t)i * HIDDEN + c * 32 + lane];

    float m = __int_as_float(0xff800000);
    float d = 0.f;
    float acc[8] = {};

    int p = start;
    for (; p + 3 < end; p += 4) {
        int c0 = g_ccol[p], c1 = g_ccol[p + 1], c2 = g_ccol[p + 2], c3 = g_ccol[p + 3];
        const float* k0r = &g_k[(size_t)c0 * HIDDEN];
        const float* k1r = &g_k[(size_t)c1 * HIDDEN];
        const float* k2r = &g_k[(size_t)c2 * HIDDEN];
        const float* k3r = &g_k[(size_t)c3 * HIDDEN];
        float s0 = 0.f, s1 = 0.f, s2 = 0.f, s3 = 0.f;
        #pragma unroll
        for (int c = 0; c < 8; c++) {
            int o = c * 32 + lane;
            s0 += ql[c] * __ldg(&k0r[o]);
            s1 += ql[c] * __ldg(&k1r[o]);
            s2 += ql[c] * __ldg(&k2r[o]);
            s3 += ql[c] * __ldg(&k3r[o]);
        }
        s0 += __shfl_xor_sync(0xffffffffu, s0, 16);
        s0 += __shfl_xor_sync(0xffffffffu, s0, 8);
        s1 += __shfl_xor_sync(0xffffffffu, s1, 16);
        s1 += __shfl_xor_sync(0xffffffffu, s1, 8);
        s2 += __shfl_xor_sync(0xffffffffu, s2, 16);
        s2 += __shfl_xor_sync(0xffffffffu, s2, 8);
        s3 += __shfl_xor_sync(0xffffffffu, s3, 16);
        s3 += __shfl_xor_sync(0xffffffffu, s3, 8);

        float m2 = fmaxf(fmaxf(fmaxf(s0, s1), fmaxf(s2, s3)), m);
        float cf = __expf(m - m2);
        float w0 = __expf(s0 - m2);
        float w1 = __expf(s1 - m2);
        float w2 = __expf(s2 - m2);
        float w3 = __expf(s3 - m2);
        d = d * cf + (w0 + w1) + (w2 + w3);
        m = m2;

        const float* v0r = &g_v[(size_t)c0 * HIDDEN];
        const float* v1r = &g_v[(size_t)c1 * HIDDEN];
        const float* v2r = &g_v[(size_t)c2 * HIDDEN];
        const float* v3r = &g_v[(size_t)c3 * HIDDEN];
        #pragma unroll
        for (int c = 0; c < 8; c++) {
            int o = c * 32 + lane;
            float t = acc[c] * cf;
            t += w0 * __ldg(&v0r[o]);
            t += w1 * __ldg(&v1r[o]);
            t += w2 * __ldg(&v2r[o]);
            t += w3 * __ldg(&v3r[o]);
            acc[c] = t;
        }
    }
    for (; p < end; p++) {
        int c0 = g_ccol[p];
        const float* kr = &g_k[(size_t)c0 * HIDDEN];
        float s0 = 0.f;
        #pragma unroll
        for (int c = 0; c < 8; c++) s0 += ql[c] * __ldg(&kr[c * 32 + lane]);
        s0 += __shfl_xor_sync(0xffffffffu, s0, 16);
        s0 += __shfl_xor_sync(0xffffffffu, s0, 8);
        float m2 = fmaxf(m, s0);
        float cf = __expf(m - m2);
        float w0 = __expf(s0 - m2);
        d = d * cf + w0;
        m = m2;
        const float* vr = &g_v[(size_t)c0 * HIDDEN];
        #pragma unroll
        for (int c = 0; c < 8; c++)
            acc[c] = acc[c] * cf + w0 * __ldg(&vr[c * 32 + lane]);
    }

    float rd = (end > start) ? 1.f / d : 0.f;
    #pragma unroll
    for (int c = 0; c < 8; c++)
        g_ao[(size_t)i * HIDDEN + c * 32 + lane] = acc[c] * rd;
}

// ---------------- launch ----------------
extern "C" void kernel_launch(void* const* d_in, const int* in_sizes, int n_in,
                              void* d_out, int out_size) {
    const float* h   = (const float*)d_in[0];
    const int*   row = (const int*)d_in[1];
    const int*   col = (const int*)d_in[2];
    const float* Wq  = (const float*)d_in[3];
    const float* bq  = (const float*)d_in[4];
    const float* Wk  = (const float*)d_in[5];
    const float* bk  = (const float*)d_in[6];
    const float* Wv  = (const float*)d_in[7];
    const float* bv  = (const float*)d_in[8];
    const float* Wo  = (const float*)d_in[9];
    const float* bo  = (const float*)d_in[10];
    float* out = (float*)d_out;

    const int N = in_sizes[0] / HIDDEN;
    const int E = in_sizes[1];

    float *pq, *pk, *pv, *pao;
    int *pdeg;
    cudaGetSymbolAddress((void**)&pq,  g_q);
    cudaGetSymbolAddress((void**)&pk,  g_k);
    cudaGetSymbolAddress((void**)&pv,  g_v);
    cudaGetSymbolAddress((void**)&pao, g_ao);
    cudaGetSymbolAddress((void**)&pdeg, g_deg);

    static int attr_set = 0;
    if (!attr_set) {
        cudaFuncSetAttribute(gemm3_kernel,
                             cudaFuncAttributeMaxDynamicSharedMemorySize, SMEM_BYTES);
        attr_set = 1;
    }

    cudaMemsetAsync(pdeg, 0, (size_t)N * sizeof(int));
    count_deg_kernel<<<(E + 255) / 256, 256>>>(row, E);
    scan_kernel<<<1, 1024>>>(N);
    scatter_kernel<<<(E + 255) / 256, 256>>>(row, col, E);

    const float scaling = 0.17677669529663687f;  // 32^-0.5
    dim3 gqkv((N + 127) / 128, HIDDEN / 64, 3);
    gemm3_kernel<<<gqkv, 256, SMEM_BYTES>>>(h, Wq, Wk, Wv, bq, bk, bv,
                                            pq, pk, pv, N, scaling);

    attn_kernel<<<(N + 7) / 8, 256>>>(N);

    dim3 go((N + 127) / 128, HIDDEN / 64, 1);
    gemm3_kernel<<<go, 256, SMEM_BYTES>>>(pao, Wo, Wo, Wo, bo, bo, bo,
                                          out, out, out, N, 1.f);
}

// round 7
// speedup vs baseline: 1.9330x; 1.3853x over previous
#include <cuda_runtime.h>
#include <cuda_fp16.h>
#include <cstdint>

#define HIDDEN 256
#define HEADS 8
#define MAXN 50000
#define MAXE 800000

// ---------------- scratch ----------------
__device__ float g_q[(size_t)MAXN * HIDDEN];
__device__ float g_k[(size_t)MAXN * HIDDEN];
__device__ float g_v[(size_t)MAXN * HIDDEN];
__device__ float g_ao[(size_t)MAXN * HIDDEN];
__device__ int   g_deg[MAXN];
__device__ int   g_offs[MAXN + 1];
__device__ int   g_cursor[MAXN];
__device__ int   g_ccol[MAXE];

// ---------------- CSR build ----------------
__global__ void count_deg_kernel(const int* __restrict__ row, int e) {
    int i = blockIdx.x * blockDim.x + threadIdx.x;
    if (i < e) atomicAdd(&g_deg[row[i]], 1);
}

__global__ void scan_kernel(int n) {
    __shared__ int wsum[32];
    int lane = threadIdx.x & 31;
    int wid  = threadIdx.x >> 5;
    int carry = 0;
    for (int base = 0; base < n; base += 1024) {
        int i = base + (int)threadIdx.x;
        int v = (i < n) ? g_deg[i] : 0;
        int x = v;
        #pragma unroll
        for (int d = 1; d < 32; d <<= 1) {
            int y = __shfl_up_sync(0xffffffffu, x, d);
            if (lane >= d) x += y;
        }
        if (lane == 31) wsum[wid] = x;
        __syncthreads();
        if (wid == 0) {
            int wv = wsum[lane];
            #pragma unroll
            for (int d = 1; d < 32; d <<= 1) {
                int y = __shfl_up_sync(0xffffffffu, wv, d);
                if (lane >= d) wv += y;
            }
            wsum[lane] = wv;
        }
        __syncthreads();
        int inc = x + (wid > 0 ? wsum[wid - 1] : 0) + carry;
        if (i < n) {
            int excl = inc - v;
            g_offs[i]   = excl;
            g_cursor[i] = excl;
        }
        carry += wsum[31];
        __syncthreads();
    }
    if (threadIdx.x == 0) g_offs[n] = carry;
}

__global__ void scatter_kernel(const int* __restrict__ row, const int* __restrict__ col, int e) {
    int i = blockIdx.x * blockDim.x + threadIdx.x;
    if (i < e) {
        int slot = atomicAdd(&g_cursor[row[i]], 1);
        g_ccol[slot] = col[i];
    }
}

// ================ fp16x3 GEMM, fragment-packed smem ================
// C[m][n] = (sum_k A[m][k]*W[n][k] + bias[n]) * scale
// BM=128 BN=128 BK=16. 8 warps, warp tile 32x64 (2 m16-tiles x 8 n8-tiles).
// smem layout per stage (16 KB):
//   Ah[8 tiles][32 lanes][16B]  (4KB)   fragment-packed: lane's {a0,a1,a2,a3}
//   Al  (4KB), Bh[16 tiles][32 lanes][8B] (4KB), Bl (4KB)
#define ST_AH 0
#define ST_AL 4096
#define ST_BH 8192
#define ST_BL 12288
#define ST_SZ 16384

__device__ __forceinline__ uint32_t packh2(float x, float y) {
    __half2 h = __halves2half2(__float2half_rn(x), __float2half_rn(y));
    return *(uint32_t*)&h;
}
__device__ __forceinline__ uint32_t packlo2(float x, float y, uint32_t h) {
    __half2 hh = *(__half2*)&h;
    float rx = x - __half2float(__low2half(hh));
    float ry = y - __half2float(__high2half(hh));
    return packh2(rx, ry);
}

#define MMA_F16(ACC, AV, B0, B1)                                           \
    asm volatile(                                                          \
        "mma.sync.aligned.m16n8k16.row.col.f32.f16.f16.f32 "              \
        "{%0,%1,%2,%3}, {%4,%5,%6,%7}, {%8,%9}, {%0,%1,%2,%3};"           \
        : "+f"(ACC[0]), "+f"(ACC[1]), "+f"(ACC[2]), "+f"(ACC[3])          \
        : "r"(AV.x), "r"(AV.y), "r"(AV.z), "r"(AV.w),                     \
          "r"(B0), "r"(B1))

__global__ void __launch_bounds__(256, 2) gemm_f16x3_kernel(
    const float* __restrict__ A,
    const float* __restrict__ W0, const float* __restrict__ W1, const float* __restrict__ W2,
    const float* __restrict__ b0_, const float* __restrict__ b1_, const float* __restrict__ b2_,
    float* __restrict__ C0, float* __restrict__ C1, float* __restrict__ C2,
    int M, float scale0)
{
    __shared__ __align__(16) unsigned char sm[2][ST_SZ];

    const int z = blockIdx.z;
    const float* W    = (z == 0) ? W0 : (z == 1) ? W1 : W2;
    const float* bias = (z == 0) ? b0_ : (z == 1) ? b1_ : b2_;
    float* C          = (z == 0) ? C0 : (z == 1) ? C1 : C2;
    const float scale = (z == 0) ? scale0 : 1.f;

    const int tid  = threadIdx.x;
    const int lane = tid & 31;
    const int warp = tid >> 5;
    const int g    = lane >> 2;
    const int tig  = lane & 3;
    const int wm   = (warp >> 1) * 32;   // 0,32,64,96
    const int wn   = (warp & 1) * 64;    // 0,64

    const int m0 = blockIdx.x * 128;
    const int n0 = blockIdx.y * 128;

    // ---- fill thread mapping ----
    const int ftr = tid >> 5;            // A tile 0..7  (rows ftr*16..+15)
    const int fl  = lane;                // fragment lane
    const int arow_lo = m0 + ftr * 16 + g;
    const int arow_hi = arow_lo + 8;
    const bool vlo = arow_lo < M, vhi = arow_hi < M;
    const float* Ap_ll = A + (size_t)arow_lo * HIDDEN + 2 * tig;       // a0 src
    const float* Ap_hl = A + (size_t)arow_hi * HIDDEN + 2 * tig;       // a1 src
    // B: tiles ftr and ftr+8 (8 n-rows each)
    const float* Wp0 = W + (size_t)(n0 + ftr * 8 + g) * HIDDEN + 2 * tig;
    const float* Wp1 = W + (size_t)(n0 + (ftr + 8) * 8 + g) * HIDDEN + 2 * tig;

    float2 xa0, xa1, xa2, xa3;   // A raw: (g,klo),(g+8,klo),(g,khi),(g+8,khi)
    float2 xb0, xb1, xb2, xb3;   // B raw: t0 klo, t0 khi, t1 klo, t1 khi

    const float2 Z2 = make_float2(0.f, 0.f);

    // prologue loads (k0 = 0)
    xa0 = vlo ? *(const float2*)(Ap_ll)     : Z2;
    xa1 = vhi ? *(const float2*)(Ap_hl)     : Z2;
    xa2 = vlo ? *(const float2*)(Ap_ll + 8) : Z2;
    xa3 = vhi ? *(const float2*)(Ap_hl + 8) : Z2;
    xb0 = *(const float2*)(Wp0);
    xb1 = *(const float2*)(Wp0 + 8);
    xb2 = *(const float2*)(Wp1);
    xb3 = *(const float2*)(Wp1 + 8);

    float acc[2][8][4];
    #pragma unroll
    for (int mt = 0; mt < 2; mt++)
        #pragma unroll
        for (int nt = 0; nt < 8; nt++)
            #pragma unroll
            for (int r = 0; r < 4; r++) acc[mt][nt][r] = 0.f;

    // store stage 0
    {
        unsigned char* st = sm[0];
        uint4 h, l;
        h.x = packh2(xa0.x, xa0.y); l.x = packlo2(xa0.x, xa0.y, h.x);
        h.y = packh2(xa1.x, xa1.y); l.y = packlo2(xa1.x, xa1.y, h.y);
        h.z = packh2(xa2.x, xa2.y); l.z = packlo2(xa2.x, xa2.y, h.z);
        h.w = packh2(xa3.x, xa3.y); l.w = packlo2(xa3.x, xa3.y, h.w);
        *(uint4*)(st + ST_AH + ftr * 512 + fl * 16) = h;
        *(uint4*)(st + ST_AL + ftr * 512 + fl * 16) = l;
        uint2 bh0, bl0, bh1, bl1;
        bh0.x = packh2(xb0.x, xb0.y); bl0.x = packlo2(xb0.x, xb0.y, bh0.x);
        bh0.y = packh2(xb1.x, xb1.y); bl0.y = packlo2(xb1.x, xb1.y, bh0.y);
        bh1.x = packh2(xb2.x, xb2.y); bl1.x = packlo2(xb2.x, xb2.y, bh1.x);
        bh1.y = packh2(xb3.x, xb3.y); bl1.y = packlo2(xb3.x, xb3.y, bh1.y);
        *(uint2*)(st + ST_BH + ftr * 256 + fl * 8) = bh0;
        *(uint2*)(st + ST_BL + ftr * 256 + fl * 8) = bl0;
        *(uint2*)(st + ST_BH + (ftr + 8) * 256 + fl * 8) = bh1;
        *(uint2*)(st + ST_BL + (ftr + 8) * 256 + fl * 8) = bl1;
    }
    __syncthreads();

    #pragma unroll 1
    for (int it = 0; it < 16; it++) {
        // prefetch next-k raw tiles into registers
        if (it + 1 < 16) {
            int ko = (it + 1) * 16;
            xa0 = vlo ? *(const float2*)(Ap_ll + ko)     : Z2;
            xa1 = vhi ? *(const float2*)(Ap_hl + ko)     : Z2;
            xa2 = vlo ? *(const float2*)(Ap_ll + ko + 8) : Z2;
            xa3 = vhi ? *(const float2*)(Ap_hl + ko + 8) : Z2;
            xb0 = *(const float2*)(Wp0 + ko);
            xb1 = *(const float2*)(Wp0 + ko + 8);
            xb2 = *(const float2*)(Wp1 + ko);
            xb3 = *(const float2*)(Wp1 + ko + 8);
        }

        // compute current stage
        {
            const unsigned char* st = sm[it & 1];
            uint4 ah[2], al[2];
            #pragma unroll
            for (int mt = 0; mt < 2; mt++) {
                int tr = (wm >> 4) + mt;
                ah[mt] = *(const uint4*)(st + ST_AH + tr * 512 + lane * 16);
                al[mt] = *(const uint4*)(st + ST_AL + tr * 512 + lane * 16);
            }
            #pragma unroll
            for (int nt = 0; nt < 8; nt++) {
                int tn = (wn >> 3) + nt;
                uint2 bh = *(const uint2*)(st + ST_BH + tn * 256 + lane * 8);
                uint2 bl = *(const uint2*)(st + ST_BL + tn * 256 + lane * 8);
                #pragma unroll
                for (int mt = 0; mt < 2; mt++) {
                    MMA_F16(acc[mt][nt], al[mt], bh.x, bh.y);
                    MMA_F16(acc[mt][nt], ah[mt], bl.x, bl.y);
                    MMA_F16(acc[mt][nt], ah[mt], bh.x, bh.y);
                }
            }
        }

        // split + store next stage
        if (it + 1 < 16) {
            unsigned char* st = sm[(it + 1) & 1];
            uint4 h, l;
            h.x = packh2(xa0.x, xa0.y); l.x = packlo2(xa0.x, xa0.y, h.x);
            h.y = packh2(xa1.x, xa1.y); l.y = packlo2(xa1.x, xa1.y, h.y);
            h.z = packh2(xa2.x, xa2.y); l.z = packlo2(xa2.x, xa2.y, h.z);
            h.w = packh2(xa3.x, xa3.y); l.w = packlo2(xa3.x, xa3.y, h.w);
            *(uint4*)(st + ST_AH + ftr * 512 + fl * 16) = h;
            *(uint4*)(st + ST_AL + ftr * 512 + fl * 16) = l;
            uint2 bh0, bl0, bh1, bl1;
            bh0.x = packh2(xb0.x, xb0.y); bl0.x = packlo2(xb0.x, xb0.y, bh0.x);
            bh0.y = packh2(xb1.x, xb1.y); bl0.y = packlo2(xb1.x, xb1.y, bh0.y);
            bh1.x = packh2(xb2.x, xb2.y); bl1.x = packlo2(xb2.x, xb2.y, bh1.x);
            bh1.y = packh2(xb3.x, xb3.y); bl1.y = packlo2(xb3.x, xb3.y, bh1.y);
            *(uint2*)(st + ST_BH + ftr * 256 + fl * 8) = bh0;
            *(uint2*)(st + ST_BL + ftr * 256 + fl * 8) = bl0;
            *(uint2*)(st + ST_BH + (ftr + 8) * 256 + fl * 8) = bh1;
            *(uint2*)(st + ST_BL + (ftr + 8) * 256 + fl * 8) = bl1;
        }
        __syncthreads();
    }

    // epilogue
    #pragma unroll
    for (int mt = 0; mt < 2; mt++) {
        int r0 = m0 + wm + mt * 16 + g;
        #pragma unroll
        for (int nt = 0; nt < 8; nt++) {
            int c = n0 + wn + nt * 8 + 2 * tig;
            float bx = bias[c], by = bias[c + 1];
            if (r0 < M) {
                float2 o0;
                o0.x = (acc[mt][nt][0] + bx) * scale;
                o0.y = (acc[mt][nt][1] + by) * scale;
                *(float2*)(C + (size_t)r0 * HIDDEN + c) = o0;
            }
            if (r0 + 8 < M) {
                float2 o1;
                o1.x = (acc[mt][nt][2] + bx) * scale;
                o1.y = (acc[mt][nt][3] + by) * scale;
                *(float2*)(C + (size_t)(r0 + 8) * HIDDEN + c) = o1;
            }
        }
    }
}

// ---------------- attention: one warp per node, 4-edge online softmax -------
__global__ void __launch_bounds__(256) attn_kernel(int n) {
    int gw   = (blockIdx.x * blockDim.x + threadIdx.x) >> 5;
    int lane = threadIdx.x & 31;
    if (gw >= n) return;
    const int i = gw;
    const int start = g_offs[i];
    const int end   = g_offs[i + 1];

    float ql[8];
    #pragma unroll
    for (int c = 0; c < 8; c++) ql[c] = g_q[(size_t)i * HIDDEN + c * 32 + lane];

    float m = __int_as_float(0xff800000);
    float d = 0.f;
    float acc[8] = {};

    int p = start;
    for (; p + 3 < end; p += 4) {
        int c0 = g_ccol[p], c1 = g_ccol[p + 1], c2 = g_ccol[p + 2], c3 = g_ccol[p + 3];
        const float* k0r = &g_k[(size_t)c0 * HIDDEN];
        const float* k1r = &g_k[(size_t)c1 * HIDDEN];
        const float* k2r = &g_k[(size_t)c2 * HIDDEN];
        const float* k3r = &g_k[(size_t)c3 * HIDDEN];
        float s0 = 0.f, s1 = 0.f, s2 = 0.f, s3 = 0.f;
        #pragma unroll
        for (int c = 0; c < 8; c++) {
            int o = c * 32 + lane;
            s0 += ql[c] * __ldg(&k0r[o]);
            s1 += ql[c] * __ldg(&k1r[o]);
            s2 += ql[c] * __ldg(&k2r[o]);
            s3 += ql[c] * __ldg(&k3r[o]);
        }
        s0 += __shfl_xor_sync(0xffffffffu, s0, 16);
        s0 += __shfl_xor_sync(0xffffffffu, s0, 8);
        s1 += __shfl_xor_sync(0xffffffffu, s1, 16);
        s1 += __shfl_xor_sync(0xffffffffu, s1, 8);
        s2 += __shfl_xor_sync(0xffffffffu, s2, 16);
        s2 += __shfl_xor_sync(0xffffffffu, s2, 8);
        s3 += __shfl_xor_sync(0xffffffffu, s3, 16);
        s3 += __shfl_xor_sync(0xffffffffu, s3, 8);

        float m2 = fmaxf(fmaxf(fmaxf(s0, s1), fmaxf(s2, s3)), m);
        float cf = __expf(m - m2);
        float w0 = __expf(s0 - m2);
        float w1 = __expf(s1 - m2);
        float w2 = __expf(s2 - m2);
        float w3 = __expf(s3 - m2);
        d = d * cf + (w0 + w1) + (w2 + w3);
        m = m2;

        const float* v0r = &g_v[(size_t)c0 * HIDDEN];
        const float* v1r = &g_v[(size_t)c1 * HIDDEN];
        const float* v2r = &g_v[(size_t)c2 * HIDDEN];
        const float* v3r = &g_v[(size_t)c3 * HIDDEN];
        #pragma unroll
        for (int c = 0; c < 8; c++) {
            int o = c * 32 + lane;
            float t = acc[c] * cf;
            t += w0 * __ldg(&v0r[o]);
            t += w1 * __ldg(&v1r[o]);
            t += w2 * __ldg(&v2r[o]);
            t += w3 * __ldg(&v3r[o]);
            acc[c] = t;
        }
    }
    for (; p < end; p++) {
        int c0 = g_ccol[p];
        const float* kr = &g_k[(size_t)c0 * HIDDEN];
        float s0 = 0.f;
        #pragma unroll
        for (int c = 0; c < 8; c++) s0 += ql[c] * __ldg(&kr[c * 32 + lane]);
        s0 += __shfl_xor_sync(0xffffffffu, s0, 16);
        s0 += __shfl_xor_sync(0xffffffffu, s0, 8);
        float m2 = fmaxf(m, s0);
        float cf = __expf(m - m2);
        float w0 = __expf(s0 - m2);
        d = d * cf + w0;
        m = m2;
        const float* vr = &g_v[(size_t)c0 * HIDDEN];
        #pragma unroll
        for (int c = 0; c < 8; c++)
            acc[c] = acc[c] * cf + w0 * __ldg(&vr[c * 32 + lane]);
    }

    float rd = (end > start) ? 1.f / d : 0.f;
    #pragma unroll
    for (int c = 0; c < 8; c++)
        g_ao[(size_t)i * HIDDEN + c * 32 + lane] = acc[c] * rd;
}

// ---------------- launch ----------------
extern "C" void kernel_launch(void* const* d_in, const int* in_sizes, int n_in,
                              void* d_out, int out_size) {
    const float* h   = (const float*)d_in[0];
    const int*   row = (const int*)d_in[1];
    const int*   col = (const int*)d_in[2];
    const float* Wq  = (const float*)d_in[3];
    const float* bq  = (const float*)d_in[4];
    const float* Wk  = (const float*)d_in[5];
    const float* bk  = (const float*)d_in[6];
    const float* Wv  = (const float*)d_in[7];
    const float* bv  = (const float*)d_in[8];
    const float* Wo  = (const float*)d_in[9];
    const float* bo  = (const float*)d_in[10];
    float* out = (float*)d_out;

    const int N = in_sizes[0] / HIDDEN;
    const int E = in_sizes[1];

    float *pq, *pk, *pv, *pao;
    int *pdeg;
    cudaGetSymbolAddress((void**)&pq,  g_q);
    cudaGetSymbolAddress((void**)&pk,  g_k);
    cudaGetSymbolAddress((void**)&pv,  g_v);
    cudaGetSymbolAddress((void**)&pao, g_ao);
    cudaGetSymbolAddress((void**)&pdeg, g_deg);

    cudaMemsetAsync(pdeg, 0, (size_t)N * sizeof(int));
    count_deg_kernel<<<(E + 255) / 256, 256>>>(row, E);
    scan_kernel<<<1, 1024>>>(N);
    scatter_kernel<<<(E + 255) / 256, 256>>>(row, col, E);

    const float scaling = 0.17677669529663687f;  // 32^-0.5
    dim3 gqkv((N + 127) / 128, HIDDEN / 128, 3);
    gemm_f16x3_kernel<<<gqkv, 256>>>(h, Wq, Wk, Wv, bq, bk, bv,
                                     pq, pk, pv, N, scaling);

    attn_kernel<<<(N + 7) / 8, 256>>>(N);

    dim3 go((N + 127) / 128, HIDDEN / 128, 1);
    gemm_f16x3_kernel<<<go, 256>>>(pao, Wo, Wo, Wo, bo, bo, bo,
                                   out, out, out, N, 1.f);
}

// round 8
// speedup vs baseline: 2.2592x; 1.1688x over previous
#include <cuda_runtime.h>
#include <cuda_fp16.h>
#include <cstdint>

#define HIDDEN 256
#define HEADS 8
#define MAXN 50000
#define MAXE 800000

// ---------------- scratch ----------------
__device__ float  g_q[(size_t)MAXN * HIDDEN];
__device__ __half g_kh[(size_t)MAXN * HIDDEN];   // paired layout: [2j]=feat j, [2j+1]=feat j+128
__device__ __half g_vh[(size_t)MAXN * HIDDEN];
__device__ float  g_ao[(size_t)MAXN * HIDDEN];
__device__ int    g_deg[MAXN];
__device__ int    g_offs[MAXN + 1];
__device__ int    g_cursor[MAXN];
__device__ int    g_ccol[MAXE];

// ---------------- CSR build ----------------
__global__ void count_deg_kernel(const int* __restrict__ row, int e) {
    int i = blockIdx.x * blockDim.x + threadIdx.x;
    if (i < e) atomicAdd(&g_deg[row[i]], 1);
}

__global__ void scan_kernel(int n) {
    __shared__ int wsum[32];
    int lane = threadIdx.x & 31;
    int wid  = threadIdx.x >> 5;
    int carry = 0;
    for (int base = 0; base < n; base += 1024) {
        int i = base + (int)threadIdx.x;
        int v = (i < n) ? g_deg[i] : 0;
        int x = v;
        #pragma unroll
        for (int d = 1; d < 32; d <<= 1) {
            int y = __shfl_up_sync(0xffffffffu, x, d);
            if (lane >= d) x += y;
        }
        if (lane == 31) wsum[wid] = x;
        __syncthreads();
        if (wid == 0) {
            int wv = wsum[lane];
            #pragma unroll
            for (int d = 1; d < 32; d <<= 1) {
                int y = __shfl_up_sync(0xffffffffu, wv, d);
                if (lane >= d) wv += y;
            }
            wsum[lane] = wv;
        }
        __syncthreads();
        int inc = x + (wid > 0 ? wsum[wid - 1] : 0) + carry;
        if (i < n) {
            int excl = inc - v;
            g_offs[i]   = excl;
            g_cursor[i] = excl;
        }
        carry += wsum[31];
        __syncthreads();
    }
    if (threadIdx.x == 0) g_offs[n] = carry;
}

__global__ void scatter_kernel(const int* __restrict__ row, const int* __restrict__ col, int e) {
    int i = blockIdx.x * blockDim.x + threadIdx.x;
    if (i < e) {
        int slot = atomicAdd(&g_cursor[row[i]], 1);
        g_ccol[slot] = col[i];
    }
}

// ================ fp16x3 GEMM, fragment-packed smem ================
// z=0 -> fp32 C0 (*scale0); z=1 -> fp16 paired KH; z=2 -> fp16 paired VH
#define ST_AH 0
#define ST_AL 4096
#define ST_BH 8192
#define ST_BL 12288
#define ST_SZ 16384

__device__ __forceinline__ uint32_t packh2(float x, float y) {
    __half2 h = __halves2half2(__float2half_rn(x), __float2half_rn(y));
    return *(uint32_t*)&h;
}
__device__ __forceinline__ uint32_t packlo2(float x, float y, uint32_t h) {
    __half2 hh = *(__half2*)&h;
    float rx = x - __half2float(__low2half(hh));
    float ry = y - __half2float(__high2half(hh));
    return packh2(rx, ry);
}

#define MMA_F16(ACC, AV, B0, B1)                                           \
    asm volatile(                                                          \
        "mma.sync.aligned.m16n8k16.row.col.f32.f16.f16.f32 "              \
        "{%0,%1,%2,%3}, {%4,%5,%6,%7}, {%8,%9}, {%0,%1,%2,%3};"           \
        : "+f"(ACC[0]), "+f"(ACC[1]), "+f"(ACC[2]), "+f"(ACC[3])          \
        : "r"(AV.x), "r"(AV.y), "r"(AV.z), "r"(AV.w),                     \
          "r"(B0), "r"(B1))

__global__ void __launch_bounds__(256, 2) gemm_f16x3_kernel(
    const float* __restrict__ A,
    const float* __restrict__ W0, const float* __restrict__ W1, const float* __restrict__ W2,
    const float* __restrict__ b0_, const float* __restrict__ b1_, const float* __restrict__ b2_,
    float* __restrict__ C0, __half* __restrict__ KH, __half* __restrict__ VH,
    int M, float scale0)
{
    __shared__ __align__(16) unsigned char sm[2][ST_SZ];

    const int z = blockIdx.z;
    const float* W    = (z == 0) ? W0 : (z == 1) ? W1 : W2;
    const float* bias = (z == 0) ? b0_ : (z == 1) ? b1_ : b2_;

    const int tid  = threadIdx.x;
    const int lane = tid & 31;
    const int warp = tid >> 5;
    const int g    = lane >> 2;
    const int tig  = lane & 3;
    const int wm   = (warp >> 1) * 32;
    const int wn   = (warp & 1) * 64;

    const int m0 = blockIdx.x * 128;
    const int n0 = blockIdx.y * 128;

    const int ftr = tid >> 5;
    const int fl  = lane;
    const int arow_lo = m0 + ftr * 16 + g;
    const int arow_hi = arow_lo + 8;
    const bool vlo = arow_lo < M, vhi = arow_hi < M;
    const float* Ap_ll = A + (size_t)arow_lo * HIDDEN + 2 * tig;
    const float* Ap_hl = A + (size_t)arow_hi * HIDDEN + 2 * tig;
    const float* Wp0 = W + (size_t)(n0 + ftr * 8 + g) * HIDDEN + 2 * tig;
    const float* Wp1 = W + (size_t)(n0 + (ftr + 8) * 8 + g) * HIDDEN + 2 * tig;

    float2 xa0, xa1, xa2, xa3;
    float2 xb0, xb1, xb2, xb3;
    const float2 Z2 = make_float2(0.f, 0.f);

    xa0 = vlo ? *(const float2*)(Ap_ll)     : Z2;
    xa1 = vhi ? *(const float2*)(Ap_hl)     : Z2;
    xa2 = vlo ? *(const float2*)(Ap_ll + 8) : Z2;
    xa3 = vhi ? *(const float2*)(Ap_hl + 8) : Z2;
    xb0 = *(const float2*)(Wp0);
    xb1 = *(const float2*)(Wp0 + 8);
    xb2 = *(const float2*)(Wp1);
    xb3 = *(const float2*)(Wp1 + 8);

    float acc[2][8][4];
    #pragma unroll
    for (int mt = 0; mt < 2; mt++)
        #pragma unroll
        for (int nt = 0; nt < 8; nt++)
            #pragma unroll
            for (int r = 0; r < 4; r++) acc[mt][nt][r] = 0.f;

    {
        unsigned char* st = sm[0];
        uint4 h, l;
        h.x = packh2(xa0.x, xa0.y); l.x = packlo2(xa0.x, xa0.y, h.x);
        h.y = packh2(xa1.x, xa1.y); l.y = packlo2(xa1.x, xa1.y, h.y);
        h.z = packh2(xa2.x, xa2.y); l.z = packlo2(xa2.x, xa2.y, h.z);
        h.w = packh2(xa3.x, xa3.y); l.w = packlo2(xa3.x, xa3.y, h.w);
        *(uint4*)(st + ST_AH + ftr * 512 + fl * 16) = h;
        *(uint4*)(st + ST_AL + ftr * 512 + fl * 16) = l;
        uint2 bh0, bl0, bh1, bl1;
        bh0.x = packh2(xb0.x, xb0.y); bl0.x = packlo2(xb0.x, xb0.y, bh0.x);
        bh0.y = packh2(xb1.x, xb1.y); bl0.y = packlo2(xb1.x, xb1.y, bh0.y);
        bh1.x = packh2(xb2.x, xb2.y); bl1.x = packlo2(xb2.x, xb2.y, bh1.x);
        bh1.y = packh2(xb3.x, xb3.y); bl1.y = packlo2(xb3.x, xb3.y, bh1.y);
        *(uint2*)(st + ST_BH + ftr * 256 + fl * 8) = bh0;
        *(uint2*)(st + ST_BL + ftr * 256 + fl * 8) = bl0;
        *(uint2*)(st + ST_BH + (ftr + 8) * 256 + fl * 8) = bh1;
        *(uint2*)(st + ST_BL + (ftr + 8) * 256 + fl * 8) = bl1;
    }
    __syncthreads();

    #pragma unroll 1
    for (int it = 0; it < 16; it++) {
        if (it + 1 < 16) {
            int ko = (it + 1) * 16;
            xa0 = vlo ? *(const float2*)(Ap_ll + ko)     : Z2;
            xa1 = vhi ? *(const float2*)(Ap_hl + ko)     : Z2;
            xa2 = vlo ? *(const float2*)(Ap_ll + ko + 8) : Z2;
            xa3 = vhi ? *(const float2*)(Ap_hl + ko + 8) : Z2;
            xb0 = *(const float2*)(Wp0 + ko);
            xb1 = *(const float2*)(Wp0 + ko + 8);
            xb2 = *(const float2*)(Wp1 + ko);
            xb3 = *(const float2*)(Wp1 + ko + 8);
        }

        {
            const unsigned char* st = sm[it & 1];
            uint4 ah[2], al[2];
            #pragma unroll
            for (int mt = 0; mt < 2; mt++) {
                int tr = (wm >> 4) + mt;
                ah[mt] = *(const uint4*)(st + ST_AH + tr * 512 + lane * 16);
                al[mt] = *(const uint4*)(st + ST_AL + tr * 512 + lane * 16);
            }
            #pragma unroll
            for (int nt = 0; nt < 8; nt++) {
                int tn = (wn >> 3) + nt;
                uint2 bh = *(const uint2*)(st + ST_BH + tn * 256 + lane * 8);
                uint2 bl = *(const uint2*)(st + ST_BL + tn * 256 + lane * 8);
                #pragma unroll
                for (int mt = 0; mt < 2; mt++) {
                    MMA_F16(acc[mt][nt], al[mt], bh.x, bh.y);
                    MMA_F16(acc[mt][nt], ah[mt], bl.x, bl.y);
                    MMA_F16(acc[mt][nt], ah[mt], bh.x, bh.y);
                }
            }
        }

        if (it + 1 < 16) {
            unsigned char* st = sm[(it + 1) & 1];
            uint4 h, l;
            h.x = packh2(xa0.x, xa0.y); l.x = packlo2(xa0.x, xa0.y, h.x);
            h.y = packh2(xa1.x, xa1.y); l.y = packlo2(xa1.x, xa1.y, h.y);
            h.z = packh2(xa2.x, xa2.y); l.z = packlo2(xa2.x, xa2.y, h.z);
            h.w = packh2(xa3.x, xa3.y); l.w = packlo2(xa3.x, xa3.y, h.w);
            *(uint4*)(st + ST_AH + ftr * 512 + fl * 16) = h;
            *(uint4*)(st + ST_AL + ftr * 512 + fl * 16) = l;
            uint2 bh0, bl0, bh1, bl1;
            bh0.x = packh2(xb0.x, xb0.y); bl0.x = packlo2(xb0.x, xb0.y, bh0.x);
            bh0.y = packh2(xb1.x, xb1.y); bl0.y = packlo2(xb1.x, xb1.y, bh0.y);
            bh1.x = packh2(xb2.x, xb2.y); bl1.x = packlo2(xb2.x, xb2.y, bh1.x);
            bh1.y = packh2(xb3.x, xb3.y); bl1.y = packlo2(xb3.x, xb3.y, bh1.y);
            *(uint2*)(st + ST_BH + ftr * 256 + fl * 8) = bh0;
            *(uint2*)(st + ST_BL + ftr * 256 + fl * 8) = bl0;
            *(uint2*)(st + ST_BH + (ftr + 8) * 256 + fl * 8) = bh1;
            *(uint2*)(st + ST_BL + (ftr + 8) * 256 + fl * 8) = bl1;
        }
        __syncthreads();
    }

    // ---- epilogue ----
    if (z == 0) {
        #pragma unroll
        for (int mt = 0; mt < 2; mt++) {
            int r0 = m0 + wm + mt * 16 + g;
            #pragma unroll
            for (int nt = 0; nt < 8; nt++) {
                int c = n0 + wn + nt * 8 + 2 * tig;
                float bx = bias[c], by = bias[c + 1];
                if (r0 < M) {
                    float2 o0;
                    o0.x = (acc[mt][nt][0] + bx) * scale0;
                    o0.y = (acc[mt][nt][1] + by) * scale0;
                    *(float2*)(C0 + (size_t)r0 * HIDDEN + c) = o0;
                }
                if (r0 + 8 < M) {
                    float2 o1;
                    o1.x = (acc[mt][nt][2] + bx) * scale0;
                    o1.y = (acc[mt][nt][3] + by) * scale0;
                    *(float2*)(C0 + (size_t)(r0 + 8) * HIDDEN + c) = o1;
                }
            }
        }
    } else {
        // fp16 paired layout: half index = row*256 + 2*(c&127) + (c>=128)
        __half* H = (z == 1) ? KH : VH;
        const int off = (n0 >= 128) ? 1 : 0;
        #pragma unroll
        for (int mt = 0; mt < 2; mt++) {
            int r0 = m0 + wm + mt * 16 + g;
            #pragma unroll
            for (int nt = 0; nt < 8; nt++) {
                int c = n0 + wn + nt * 8 + 2 * tig;
                int j = c - n0;
                float bx = bias[c], by = bias[c + 1];
                if (r0 < M) {
                    __half* p = H + (size_t)r0 * HIDDEN + 2 * j + off;
                    p[0] = __float2half_rn(acc[mt][nt][0] + bx);
                    p[2] = __float2half_rn(acc[mt][nt][1] + by);
                }
                if (r0 + 8 < M) {
                    __half* p = H + (size_t)(r0 + 8) * HIDDEN + 2 * j + off;
                    p[0] = __float2half_rn(acc[mt][nt][2] + bx);
                    p[2] = __float2half_rn(acc[mt][nt][3] + by);
                }
            }
        }
    }
}

// ---------------- attention: one warp per node, fp16 K/V, 4-edge unroll -----
// paired layout: word j (j=c*32+lane) = (feat j, feat j+128); head = lane%8
__global__ void __launch_bounds__(256) attn_kernel(int n) {
    int gw   = (blockIdx.x * blockDim.x + threadIdx.x) >> 5;
    int lane = threadIdx.x & 31;
    if (gw >= n) return;
    const int i = gw;
    const int start = g_offs[i];
    const int end   = g_offs[i + 1];

    float2 ql[4];
    #pragma unroll
    for (int c = 0; c < 4; c++) {
        ql[c].x = g_q[(size_t)i * HIDDEN + c * 32 + lane];
        ql[c].y = g_q[(size_t)i * HIDDEN + c * 32 + lane + 128];
    }

    float m = __int_as_float(0xff800000);
    float d = 0.f;
    float2 acc[4] = {};

    int p = start;
    for (; p + 3 < end; p += 4) {
        int c0 = g_ccol[p], c1 = g_ccol[p + 1], c2 = g_ccol[p + 2], c3 = g_ccol[p + 3];
        const __half2* k0r = (const __half2*)&g_kh[(size_t)c0 * HIDDEN];
        const __half2* k1r = (const __half2*)&g_kh[(size_t)c1 * HIDDEN];
        const __half2* k2r = (const __half2*)&g_kh[(size_t)c2 * HIDDEN];
        const __half2* k3r = (const __half2*)&g_kh[(size_t)c3 * HIDDEN];
        float s0 = 0.f, s1 = 0.f, s2 = 0.f, s3 = 0.f;
        #pragma unroll
        for (int c = 0; c < 4; c++) {
            int o = c * 32 + lane;
            float2 k0 = __half22float2(__ldg(&k0r[o]));
            float2 k1 = __half22float2(__ldg(&k1r[o]));
            float2 k2 = __half22float2(__ldg(&k2r[o]));
            float2 k3 = __half22float2(__ldg(&k3r[o]));
            s0 += ql[c].x * k0.x + ql[c].y * k0.y;
            s1 += ql[c].x * k1.x + ql[c].y * k1.y;
            s2 += ql[c].x * k2.x + ql[c].y * k2.y;
            s3 += ql[c].x * k3.x + ql[c].y * k3.y;
        }
        s0 += __shfl_xor_sync(0xffffffffu, s0, 16);
        s0 += __shfl_xor_sync(0xffffffffu, s0, 8);
        s1 += __shfl_xor_sync(0xffffffffu, s1, 16);
        s1 += __shfl_xor_sync(0xffffffffu, s1, 8);
        s2 += __shfl_xor_sync(0xffffffffu, s2, 16);
        s2 += __shfl_xor_sync(0xffffffffu, s2, 8);
        s3 += __shfl_xor_sync(0xffffffffu, s3, 16);
        s3 += __shfl_xor_sync(0xffffffffu, s3, 8);

        float m2 = fmaxf(fmaxf(fmaxf(s0, s1), fmaxf(s2, s3)), m);
        float cf = __expf(m - m2);
        float w0 = __expf(s0 - m2);
        float w1 = __expf(s1 - m2);
        float w2 = __expf(s2 - m2);
        float w3 = __expf(s3 - m2);
        d = d * cf + (w0 + w1) + (w2 + w3);
        m = m2;

        const __half2* v0r = (const __half2*)&g_vh[(size_t)c0 * HIDDEN];
        const __half2* v1r = (const __half2*)&g_vh[(size_t)c1 * HIDDEN];
        const __half2* v2r = (const __half2*)&g_vh[(size_t)c2 * HIDDEN];
        const __half2* v3r = (const __half2*)&g_vh[(size_t)c3 * HIDDEN];
        #pragma unroll
        for (int c = 0; c < 4; c++) {
            int o = c * 32 + lane;
            float2 v0 = __half22float2(__ldg(&v0r[o]));
            float2 v1 = __half22float2(__ldg(&v1r[o]));
            float2 v2 = __half22float2(__ldg(&v2r[o]));
            float2 v3 = __half22float2(__ldg(&v3r[o]));
            float tx = acc[c].x * cf, ty = acc[c].y * cf;
            tx += w0 * v0.x + w1 * v1.x + w2 * v2.x + w3 * v3.x;
            ty += w0 * v0.y + w1 * v1.y + w2 * v2.y + w3 * v3.y;
            acc[c].x = tx; acc[c].y = ty;
        }
    }
    for (; p < end; p++) {
        int c0 = g_ccol[p];
        const __half2* kr = (const __half2*)&g_kh[(size_t)c0 * HIDDEN];
        float s0 = 0.f;
        #pragma unroll
        for (int c = 0; c < 4; c++) {
            float2 kf = __half22float2(__ldg(&kr[c * 32 + lane]));
            s0 += ql[c].x * kf.x + ql[c].y * kf.y;
        }
        s0 += __shfl_xor_sync(0xffffffffu, s0, 16);
        s0 += __shfl_xor_sync(0xffffffffu, s0, 8);
        float m2 = fmaxf(m, s0);
        float cf = __expf(m - m2);
        float w0 = __expf(s0 - m2);
        d = d * cf + w0;
        m = m2;
        const __half2* vr = (const __half2*)&g_vh[(size_t)c0 * HIDDEN];
        #pragma unroll
        for (int c = 0; c < 4; c++) {
            float2 vf = __half22float2(__ldg(&vr[c * 32 + lane]));
            acc[c].x = acc[c].x * cf + w0 * vf.x;
            acc[c].y = acc[c].y * cf + w0 * vf.y;
        }
    }

    float rd = (end > start) ? 1.f / d : 0.f;
    #pragma unroll
    for (int c = 0; c < 4; c++) {
        g_ao[(size_t)i * HIDDEN + c * 32 + lane]       = acc[c].x * rd;
        g_ao[(size_t)i * HIDDEN + c * 32 + lane + 128] = acc[c].y * rd;
    }
}

// ---------------- launch ----------------
extern "C" void kernel_launch(void* const* d_in, const int* in_sizes, int n_in,
                              void* d_out, int out_size) {
    const float* h   = (const float*)d_in[0];
    const int*   row = (const int*)d_in[1];
    const int*   col = (const int*)d_in[2];
    const float* Wq  = (const float*)d_in[3];
    const float* bq  = (const float*)d_in[4];
    const float* Wk  = (const float*)d_in[5];
    const float* bk  = (const float*)d_in[6];
    const float* Wv  = (const float*)d_in[7];
    const float* bv  = (const float*)d_in[8];
    const float* Wo  = (const float*)d_in[9];
    const float* bo  = (const float*)d_in[10];
    float* out = (float*)d_out;

    const int N = in_sizes[0] / HIDDEN;
    const int E = in_sizes[1];

    float *pq, *pao;
    __half *pkh, *pvh;
    int *pdeg;
    cudaGetSymbolAddress((void**)&pq,  g_q);
    cudaGetSymbolAddress((void**)&pkh, g_kh);
    cudaGetSymbolAddress((void**)&pvh, g_vh);
    cudaGetSymbolAddress((void**)&pao, g_ao);
    cudaGetSymbolAddress((void**)&pdeg, g_deg);

    cudaMemsetAsync(pdeg, 0, (size_t)N * sizeof(int));
    count_deg_kernel<<<(E + 255) / 256, 256>>>(row, E);
    scan_kernel<<<1, 1024>>>(N);
    scatter_kernel<<<(E + 255) / 256, 256>>>(row, col, E);

    const float scaling = 0.17677669529663687f;  // 32^-0.5
    dim3 gqkv((N + 127) / 128, HIDDEN / 128, 3);
    gemm_f16x3_kernel<<<gqkv, 256>>>(h, Wq, Wk, Wv, bq, bk, bv,
                                     pq, pkh, pvh, N, scaling);

    attn_kernel<<<(N + 7) / 8, 256>>>(N);

    dim3 go((N + 127) / 128, HIDDEN / 128, 1);
    gemm_f16x3_kernel<<<go, 256>>>(pao, Wo, Wo, Wo, bo, bo, bo,
                                   out, pkh, pvh, N, 1.f);
}

// round 9
// speedup vs baseline: 2.3847x; 1.0555x over previous
#include <cuda_runtime.h>
#include <cuda_fp16.h>
#include <cstdint>

#define HIDDEN 256
#define HEADS 8
#define MAXN 50000
#define MAXE 800000

// ---------------- scratch ----------------
__device__ float  g_q[(size_t)MAXN * HIDDEN];
__device__ __half g_kh[(size_t)MAXN * HIDDEN];  // permuted-feature layout (see below)
__device__ __half g_vh[(size_t)MAXN * HIDDEN];
__device__ float  g_ao[(size_t)MAXN * HIDDEN];
__device__ int    g_deg[MAXN];
__device__ int    g_offs[MAXN + 1];
__device__ int    g_cursor[MAXN];
__device__ int    g_ccol[MAXE];

// Layout: half index n0+jl of a row holds feature f = n0 + (jl&1)*64 + (jl>>1).
// => word w (half2) = feats (w, w+64) for w<64, (w+64, w+128) for w>=64.
//    Both feats of a word share head w%8; lane l, chunk c reads word c*32+l -> head l%8.

// ---------------- CSR build ----------------
__global__ void count_deg_kernel(const int* __restrict__ row, int e) {
    int i = blockIdx.x * blockDim.x + threadIdx.x;
    if (i < e) atomicAdd(&g_deg[row[i]], 1);
}

__global__ void scan_kernel(int n) {
    __shared__ int wsum[32];
    int lane = threadIdx.x & 31;
    int wid  = threadIdx.x >> 5;
    int carry = 0;
    for (int base = 0; base < n; base += 1024) {
        int i = base + (int)threadIdx.x;
        int v = (i < n) ? g_deg[i] : 0;
        int x = v;
        #pragma unroll
        for (int d = 1; d < 32; d <<= 1) {
            int y = __shfl_up_sync(0xffffffffu, x, d);
            if (lane >= d) x += y;
        }
        if (lane == 31) wsum[wid] = x;
        __syncthreads();
        if (wid == 0) {
            int wv = wsum[lane];
            #pragma unroll
            for (int d = 1; d < 32; d <<= 1) {
                int y = __shfl_up_sync(0xffffffffu, wv, d);
                if (lane >= d) wv += y;
            }
            wsum[lane] = wv;
        }
        __syncthreads();
        int inc = x + (wid > 0 ? wsum[wid - 1] : 0) + carry;
        if (i < n) {
            int excl = inc - v;
            g_offs[i]   = excl;
            g_cursor[i] = excl;
        }
        carry += wsum[31];
        __syncthreads();
    }
    if (threadIdx.x == 0) g_offs[n] = carry;
}

__global__ void scatter_kernel(const int* __restrict__ row, const int* __restrict__ col, int e) {
    int i = blockIdx.x * blockDim.x + threadIdx.x;
    if (i < e) {
        int slot = atomicAdd(&g_cursor[row[i]], 1);
        g_ccol[slot] = col[i];
    }
}

// ================ fp16x3 GEMM, fragment-packed smem ================
#define ST_AH 0
#define ST_AL 4096
#define ST_BH 8192
#define ST_BL 12288
#define ST_SZ 16384

__device__ __forceinline__ uint32_t packh2(float x, float y) {
    __half2 h = __halves2half2(__float2half_rn(x), __float2half_rn(y));
    return *(uint32_t*)&h;
}
__device__ __forceinline__ uint32_t packlo2(float x, float y, uint32_t h) {
    __half2 hh = *(__half2*)&h;
    float rx = x - __half2float(__low2half(hh));
    float ry = y - __half2float(__high2half(hh));
    return packh2(rx, ry);
}

#define MMA_F16(ACC, AV, B0, B1)                                           \
    asm volatile(                                                          \
        "mma.sync.aligned.m16n8k16.row.col.f32.f16.f16.f32 "              \
        "{%0,%1,%2,%3}, {%4,%5,%6,%7}, {%8,%9}, {%0,%1,%2,%3};"           \
        : "+f"(ACC[0]), "+f"(ACC[1]), "+f"(ACC[2]), "+f"(ACC[3])          \
        : "r"(AV.x), "r"(AV.y), "r"(AV.z), "r"(AV.w),                     \
          "r"(B0), "r"(B1))

__global__ void __launch_bounds__(256, 2) gemm_f16x3_kernel(
    const float* __restrict__ A,
    const float* __restrict__ W0, const float* __restrict__ W1, const float* __restrict__ W2,
    const float* __restrict__ b0_, const float* __restrict__ b1_, const float* __restrict__ b2_,
    float* __restrict__ C0, __half* __restrict__ KH, __half* __restrict__ VH,
    int M, float scale0)
{
    __shared__ __align__(16) unsigned char sm[2][ST_SZ];

    const int z = blockIdx.z;
    const float* W    = (z == 0) ? W0 : (z == 1) ? W1 : W2;
    const float* bias = (z == 0) ? b0_ : (z == 1) ? b1_ : b2_;

    const int tid  = threadIdx.x;
    const int lane = tid & 31;
    const int warp = tid >> 5;
    const int g    = lane >> 2;
    const int tig  = lane & 3;
    const int wm   = (warp >> 1) * 32;
    const int wn   = (warp & 1) * 64;

    const int m0 = blockIdx.x * 128;
    const int n0 = blockIdx.y * 128;

    const int ftr = tid >> 5;
    const int fl  = lane;
    const int arow_lo = m0 + ftr * 16 + g;
    const int arow_hi = arow_lo + 8;
    const bool vlo = arow_lo < M, vhi = arow_hi < M;
    const float* Ap_ll = A + (size_t)arow_lo * HIDDEN + 2 * tig;
    const float* Ap_hl = A + (size_t)arow_hi * HIDDEN + 2 * tig;

    // W rows: permuted for z!=0 so the fp16 epilogue is contiguous
    const int jl0 = ftr * 8 + g;
    const int jl1 = (ftr + 8) * 8 + g;
    const int wr0 = (z == 0) ? (n0 + jl0) : (n0 + ((jl0 & 1) << 6) + (jl0 >> 1));
    const int wr1 = (z == 0) ? (n0 + jl1) : (n0 + ((jl1 & 1) << 6) + (jl1 >> 1));
    const float* Wp0 = W + (size_t)wr0 * HIDDEN + 2 * tig;
    const float* Wp1 = W + (size_t)wr1 * HIDDEN + 2 * tig;

    float2 xa0, xa1, xa2, xa3;
    float2 xb0, xb1, xb2, xb3;
    const float2 Z2 = make_float2(0.f, 0.f);

    xa0 = vlo ? *(const float2*)(Ap_ll)     : Z2;
    xa1 = vhi ? *(const float2*)(Ap_hl)     : Z2;
    xa2 = vlo ? *(const float2*)(Ap_ll + 8) : Z2;
    xa3 = vhi ? *(const float2*)(Ap_hl + 8) : Z2;
    xb0 = *(const float2*)(Wp0);
    xb1 = *(const float2*)(Wp0 + 8);
    xb2 = *(const float2*)(Wp1);
    xb3 = *(const float2*)(Wp1 + 8);

    float acc[2][8][4];
    #pragma unroll
    for (int mt = 0; mt < 2; mt++)
        #pragma unroll
        for (int nt = 0; nt < 8; nt++)
            #pragma unroll
            for (int r = 0; r < 4; r++) acc[mt][nt][r] = 0.f;

    {
        unsigned char* st = sm[0];
        uint4 h, l;
        h.x = packh2(xa0.x, xa0.y); l.x = packlo2(xa0.x, xa0.y, h.x);
        h.y = packh2(xa1.x, xa1.y); l.y = packlo2(xa1.x, xa1.y, h.y);
        h.z = packh2(xa2.x, xa2.y); l.z = packlo2(xa2.x, xa2.y, h.z);
        h.w = packh2(xa3.x, xa3.y); l.w = packlo2(xa3.x, xa3.y, h.w);
        *(uint4*)(st + ST_AH + ftr * 512 + fl * 16) = h;
        *(uint4*)(st + ST_AL + ftr * 512 + fl * 16) = l;
        uint2 bh0, bl0, bh1, bl1;
        bh0.x = packh2(xb0.x, xb0.y); bl0.x = packlo2(xb0.x, xb0.y, bh0.x);
        bh0.y = packh2(xb1.x, xb1.y); bl0.y = packlo2(xb1.x, xb1.y, bh0.y);
        bh1.x = packh2(xb2.x, xb2.y); bl1.x = packlo2(xb2.x, xb2.y, bh1.x);
        bh1.y = packh2(xb3.x, xb3.y); bl1.y = packlo2(xb3.x, xb3.y, bh1.y);
        *(uint2*)(st + ST_BH + ftr * 256 + fl * 8) = bh0;
        *(uint2*)(st + ST_BL + ftr * 256 + fl * 8) = bl0;
        *(uint2*)(st + ST_BH + (ftr + 8) * 256 + fl * 8) = bh1;
        *(uint2*)(st + ST_BL + (ftr + 8) * 256 + fl * 8) = bl1;
    }
    __syncthreads();

    #pragma unroll 1
    for (int it = 0; it < 16; it++) {
        if (it + 1 < 16) {
            int ko = (it + 1) * 16;
            xa0 = vlo ? *(const float2*)(Ap_ll + ko)     : Z2;
            xa1 = vhi ? *(const float2*)(Ap_hl + ko)     : Z2;
            xa2 = vlo ? *(const float2*)(Ap_ll + ko + 8) : Z2;
            xa3 = vhi ? *(const float2*)(Ap_hl + ko + 8) : Z2;
            xb0 = *(const float2*)(Wp0 + ko);
            xb1 = *(const float2*)(Wp0 + ko + 8);
            xb2 = *(const float2*)(Wp1 + ko);
            xb3 = *(const float2*)(Wp1 + ko + 8);
        }

        {
            const unsigned char* st = sm[it & 1];
            uint4 ah[2], al[2];
            #pragma unroll
            for (int mt = 0; mt < 2; mt++) {
                int tr = (wm >> 4) + mt;
                ah[mt] = *(const uint4*)(st + ST_AH + tr * 512 + lane * 16);
                al[mt] = *(const uint4*)(st + ST_AL + tr * 512 + lane * 16);
            }
            #pragma unroll
            for (int nt = 0; nt < 8; nt++) {
                int tn = (wn >> 3) + nt;
                uint2 bh = *(const uint2*)(st + ST_BH + tn * 256 + lane * 8);
                uint2 bl = *(const uint2*)(st + ST_BL + tn * 256 + lane * 8);
                #pragma unroll
                for (int mt = 0; mt < 2; mt++) {
                    MMA_F16(acc[mt][nt], al[mt], bh.x, bh.y);
                    MMA_F16(acc[mt][nt], ah[mt], bl.x, bl.y);
                    MMA_F16(acc[mt][nt], ah[mt], bh.x, bh.y);
                }
            }
        }

        if (it + 1 < 16) {
            unsigned char* st = sm[(it + 1) & 1];
            uint4 h, l;
            h.x = packh2(xa0.x, xa0.y); l.x = packlo2(xa0.x, xa0.y, h.x);
            h.y = packh2(xa1.x, xa1.y); l.y = packlo2(xa1.x, xa1.y, h.y);
            h.z = packh2(xa2.x, xa2.y); l.z = packlo2(xa2.x, xa2.y, h.z);
            h.w = packh2(xa3.x, xa3.y); l.w = packlo2(xa3.x, xa3.y, h.w);
            *(uint4*)(st + ST_AH + ftr * 512 + fl * 16) = h;
            *(uint4*)(st + ST_AL + ftr * 512 + fl * 16) = l;
            uint2 bh0, bl0, bh1, bl1;
            bh0.x = packh2(xb0.x, xb0.y); bl0.x = packlo2(xb0.x, xb0.y, bh0.x);
            bh0.y = packh2(xb1.x, xb1.y); bl0.y = packlo2(xb1.x, xb1.y, bh0.y);
            bh1.x = packh2(xb2.x, xb2.y); bl1.x = packlo2(xb2.x, xb2.y, bh1.x);
            bh1.y = packh2(xb3.x, xb3.y); bl1.y = packlo2(xb3.x, xb3.y, bh1.y);
            *(uint2*)(st + ST_BH + ftr * 256 + fl * 8) = bh0;
            *(uint2*)(st + ST_BL + ftr * 256 + fl * 8) = bl0;
            *(uint2*)(st + ST_BH + (ftr + 8) * 256 + fl * 8) = bh1;
            *(uint2*)(st + ST_BL + (ftr + 8) * 256 + fl * 8) = bl1;
        }
        __syncthreads();
    }

    // ---- epilogue ----
    if (z == 0) {
        #pragma unroll
        for (int mt = 0; mt < 2; mt++) {
            int r0 = m0 + wm + mt * 16 + g;
            #pragma unroll
            for (int nt = 0; nt < 8; nt++) {
                int c = n0 + wn + nt * 8 + 2 * tig;
                float bx = bias[c], by = bias[c + 1];
                if (r0 < M) {
                    float2 o0;
                    o0.x = (acc[mt][nt][0] + bx) * scale0;
                    o0.y = (acc[mt][nt][1] + by) * scale0;
                    *(float2*)(C0 + (size_t)r0 * HIDDEN + c) = o0;
                }
                if (r0 + 8 < M) {
                    float2 o1;
                    o1.x = (acc[mt][nt][2] + bx) * scale0;
                    o1.y = (acc[mt][nt][3] + by) * scale0;
                    *(float2*)(C0 + (size_t)(r0 + 8) * HIDDEN + c) = o1;
                }
            }
        }
    } else {
        // contiguous: half idx n0+jl holds feat n0+(jl&1)*64+(jl>>1); bias permuted
        __half* H = (z == 1) ? KH : VH;
        #pragma unroll
        for (int mt = 0; mt < 2; mt++) {
            int r0 = m0 + wm + mt * 16 + g;
            #pragma unroll
            for (int nt = 0; nt < 8; nt++) {
                int jl = wn + nt * 8 + 2 * tig;     // even
                float bx = bias[n0 + (jl >> 1)];
                float by = bias[n0 + 64 + (jl >> 1)];
                if (r0 < M) {
                    *(__half2*)(H + (size_t)r0 * HIDDEN + n0 + jl) =
                        __halves2half2(__float2half_rn(acc[mt][nt][0] + bx),
                                       __float2half_rn(acc[mt][nt][1] + by));
                }
                if (r0 + 8 < M) {
                    *(__half2*)(H + (size_t)(r0 + 8) * HIDDEN + n0 + jl) =
                        __halves2half2(__float2half_rn(acc[mt][nt][2] + bx),
                                       __float2half_rn(acc[mt][nt][3] + by));
                }
            }
        }
    }
}

// ---------------- attention: one warp per node, fp16 K/V, 8-edge unroll -----
__global__ void __launch_bounds__(256) attn_kernel(int n) {
    int gw   = (blockIdx.x * blockDim.x + threadIdx.x) >> 5;
    int lane = threadIdx.x & 31;
    if (gw >= n) return;
    const int i = gw;
    const int start = g_offs[i];
    const int end   = g_offs[i + 1];

    // ql[c] = feats (fx, fx+64), fx = c*32+lane (+64 for c>=2)
    float2 ql[4];
    #pragma unroll
    for (int c = 0; c < 4; c++) {
        int fx = c * 32 + lane + ((c >= 2) ? 64 : 0);
        ql[c].x = g_q[(size_t)i * HIDDEN + fx];
        ql[c].y = g_q[(size_t)i * HIDDEN + fx + 64];
    }

    float m = __int_as_float(0xff800000);
    float d = 0.f;
    float2 acc[4] = {};

    const __half2* KB = (const __half2*)g_kh;
    const __half2* VB = (const __half2*)g_vh;

    int p = start;
    for (; p + 7 < end; p += 8) {
        int cn[8];
        #pragma unroll
        for (int e = 0; e < 8; e++) cn[e] = g_ccol[p + e];

        float s[8] = {0.f, 0.f, 0.f, 0.f, 0.f, 0.f, 0.f, 0.f};
        #pragma unroll
        for (int c = 0; c < 4; c++) {
            int o = c * 32 + lane;
            #pragma unroll
            for (int e = 0; e < 8; e++) {
                float2 kf = __half22float2(__ldg(KB + (size_t)cn[e] * 128 + o));
                s[e] += ql[c].x * kf.x + ql[c].y * kf.y;
            }
        }
        #pragma unroll
        for (int e = 0; e < 8; e++) {
            s[e] += __shfl_xor_sync(0xffffffffu, s[e], 16);
            s[e] += __shfl_xor_sync(0xffffffffu, s[e], 8);
        }

        float m2 = m;
        #pragma unroll
        for (int e = 0; e < 8; e++) m2 = fmaxf(m2, s[e]);
        float cf = __expf(m - m2);
        float w[8], sw = 0.f;
        #pragma unroll
        for (int e = 0; e < 8; e++) { w[e] = __expf(s[e] - m2); sw += w[e]; }
        d = d * cf + sw;
        m = m2;

        #pragma unroll
        for (int c = 0; c < 4; c++) {
            int o = c * 32 + lane;
            float tx = acc[c].x * cf, ty = acc[c].y * cf;
            #pragma unroll
            for (int e = 0; e < 8; e++) {
                float2 vf = __half22float2(__ldg(VB + (size_t)cn[e] * 128 + o));
                tx += w[e] * vf.x;
                ty += w[e] * vf.y;
            }
            acc[c].x = tx; acc[c].y = ty;
        }
    }
    for (; p < end; p++) {
        int c0 = g_ccol[p];
        float s0 = 0.f;
        #pragma unroll
        for (int c = 0; c < 4; c++) {
            float2 kf = __half22float2(__ldg(KB + (size_t)c0 * 128 + c * 32 + lane));
            s0 += ql[c].x * kf.x + ql[c].y * kf.y;
        }
        s0 += __shfl_xor_sync(0xffffffffu, s0, 16);
        s0 += __shfl_xor_sync(0xffffffffu, s0, 8);
        float m2 = fmaxf(m, s0);
        float cf = __expf(m - m2);
        float w0 = __expf(s0 - m2);
        d = d * cf + w0;
        m = m2;
        #pragma unroll
        for (int c = 0; c < 4; c++) {
            float2 vf = __half22float2(__ldg(VB + (size_t)c0 * 128 + c * 32 + lane));
            acc[c].x = acc[c].x * cf + w0 * vf.x;
            acc[c].y = acc[c].y * cf + w0 * vf.y;
        }
    }

    float rd = (end > start) ? 1.f / d : 0.f;
    #pragma unroll
    for (int c = 0; c < 4; c++) {
        int fx = c * 32 + lane + ((c >= 2) ? 64 : 0);
        g_ao[(size_t)i * HIDDEN + fx]      = acc[c].x * rd;
        g_ao[(size_t)i * HIDDEN + fx + 64] = acc[c].y * rd;
    }
}

// ---------------- launch ----------------
extern "C" void kernel_launch(void* const* d_in, const int* in_sizes, int n_in,
                              void* d_out, int out_size) {
    const float* h   = (const float*)d_in[0];
    const int*   row = (const int*)d_in[1];
    const int*   col = (const int*)d_in[2];
    const float* Wq  = (const float*)d_in[3];
    const float* bq  = (const float*)d_in[4];
    const float* Wk  = (const float*)d_in[5];
    const float* bk  = (const float*)d_in[6];
    const float* Wv  = (const float*)d_in[7];
    const float* bv  = (const float*)d_in[8];
    const float* Wo  = (const float*)d_in[9];
    const float* bo  = (const float*)d_in[10];
    float* out = (float*)d_out;

    const int N = in_sizes[0] / HIDDEN;
    const int E = in_sizes[1];

    float *pq, *pao;
    __half *pkh, *pvh;
    int *pdeg;
    cudaGetSymbolAddress((void**)&pq,  g_q);
    cudaGetSymbolAddress((void**)&pkh, g_kh);
    cudaGetSymbolAddress((void**)&pvh, g_vh);
    cudaGetSymbolAddress((void**)&pao, g_ao);
    cudaGetSymbolAddress((void**)&pdeg, g_deg);

    static cudaStream_t s2 = nullptr;
    static cudaEvent_t evFork = nullptr, evJoin = nullptr;
    if (!s2) {
        cudaStreamCreateWithFlags(&s2, cudaStreamNonBlocking);
        cudaEventCreateWithFlags(&evFork, cudaEventDisableTiming);
        cudaEventCreateWithFlags(&evJoin, cudaEventDisableTiming);
    }

    // fork: CSR build on s2, QKV GEMM on main stream
    cudaEventRecord(evFork, 0);
    cudaStreamWaitEvent(s2, evFork, 0);
    cudaMemsetAsync(pdeg, 0, (size_t)N * sizeof(int), s2);
    count_deg_kernel<<<(E + 255) / 256, 256, 0, s2>>>(row, E);
    scan_kernel<<<1, 1024, 0, s2>>>(N);
    scatter_kernel<<<(E + 255) / 256, 256, 0, s2>>>(row, col, E);
    cudaEventRecord(evJoin, s2);

    const float scaling = 0.17677669529663687f;  // 32^-0.5
    dim3 gqkv((N + 127) / 128, HIDDEN / 128, 3);
    gemm_f16x3_kernel<<<gqkv, 256>>>(h, Wq, Wk, Wv, bq, bk, bv,
                                     pq, pkh, pvh, N, scaling);

    // join: attention needs CSR + QKV
    cudaStreamWaitEvent(0, evJoin, 0);
    attn_kernel<<<(N + 7) / 8, 256>>>(N);

    dim3 go((N + 127) / 128, HIDDEN / 128, 1);
    gemm_f16x3_kernel<<<go, 256>>>(pao, Wo, Wo, Wo, bo, bo, bo,
                                   out, pkh, pvh, N, 1.f);
}